// round 3
// baseline (speedup 1.0000x reference)
#include <cuda_runtime.h>
#include <math.h>

#define Bc   8
#define Nc   1025
#define Dc   768
#define Hc   12
#define HDc  64
#define E3c  2304
#define Mc   (Bc*Nc)      // 8200
#define QKPAD 68
#define ATTN_SMEM ((64*QKPAD*2 + 64*64*2)*4)   // Qst + Kst + Vs + Ps = 67584 B

// ---------------- scratch (static device globals; no runtime alloc) ----------
__device__ float g_mu [Mc];
__device__ float g_rs [Mc];
__device__ float g_qkv[(size_t)Mc * E3c];                 // [M][3][H][64]
__device__ float g_q  [(size_t)Bc * Hc * Nc * HDc];       // [B][H][N][64]
__device__ float g_k  [(size_t)Bc * Hc * Nc * HDc];
__device__ float g_v  [(size_t)Bc * Hc * Nc * HDc];
__device__ float g_o  [(size_t)Bc * Hc * Nc * HDc];

// ---------------- 1) LayerNorm row stats ------------------------------------
__global__ __launch_bounds__(256) void ln_stats_k(const float* __restrict__ x)
{
    const int row = blockIdx.x;
    const float* xr = x + (size_t)row * Dc;
    float s = 0.f, s2 = 0.f;
    for (int i = threadIdx.x; i < Dc; i += 256) {
        float v = xr[i];
        s += v; s2 += v * v;
    }
    #pragma unroll
    for (int o = 16; o; o >>= 1) {
        s  += __shfl_xor_sync(0xffffffffu, s,  o);
        s2 += __shfl_xor_sync(0xffffffffu, s2, o);
    }
    __shared__ float sh[16];
    const int w = threadIdx.x >> 5;
    if ((threadIdx.x & 31) == 0) { sh[w] = s; sh[8 + w] = s2; }
    __syncthreads();
    if (threadIdx.x < 32) {
        s  = (threadIdx.x < 8) ? sh[threadIdx.x]     : 0.f;
        s2 = (threadIdx.x < 8) ? sh[8 + threadIdx.x] : 0.f;
        #pragma unroll
        for (int o = 4; o; o >>= 1) {
            s  += __shfl_xor_sync(0xffffffffu, s,  o);
            s2 += __shfl_xor_sync(0xffffffffu, s2, o);
        }
        if (threadIdx.x == 0) {
            float mu  = s  * (1.f / Dc);
            float var = s2 * (1.f / Dc) - mu * mu;
            g_mu[row] = mu;
            g_rs[row] = rsqrtf(var + 1e-5f);
        }
    }
}

// ---------------- 2) QKV GEMM (LN fused into A loads) ------------------------
// C[m, e] = sum_d LN(x)[m,d] * w_qkv[e,d]       (M=8200, E=2304, K=768)
__global__ __launch_bounds__(256) void gemm_qkv_k(
    const float* __restrict__ x,  const float* __restrict__ lg,
    const float* __restrict__ lb, const float* __restrict__ w)
{
    __shared__ float As[8][128];
    __shared__ float Bs[8][128];
    const int tid = threadIdx.x;
    const int m0 = blockIdx.y * 128;
    const int e0 = blockIdx.x * 128;
    const int lr = tid >> 1;
    const int lk = (tid & 1) * 4;
    const int row = m0 + lr;
    const bool rok = row < Mc;
    const float mu = rok ? g_mu[row] : 0.f;
    const float rs = rok ? g_rs[row] : 0.f;
    const int trow = (tid >> 4) * 8;
    const int tcol = (tid & 15) * 8;
    float acc[8][8];
    #pragma unroll
    for (int i = 0; i < 8; i++)
        #pragma unroll
        for (int j = 0; j < 8; j++) acc[i][j] = 0.f;

    for (int k0 = 0; k0 < Dc; k0 += 8) {
        float4 xa = make_float4(0.f, 0.f, 0.f, 0.f);
        if (rok) xa = *(const float4*)(x + (size_t)row * Dc + k0 + lk);
        float4 ga = *(const float4*)(lg + k0 + lk);
        float4 ba = *(const float4*)(lb + k0 + lk);
        As[lk + 0][lr] = rok ? ((xa.x - mu) * rs * ga.x + ba.x) : 0.f;
        As[lk + 1][lr] = rok ? ((xa.y - mu) * rs * ga.y + ba.y) : 0.f;
        As[lk + 2][lr] = rok ? ((xa.z - mu) * rs * ga.z + ba.z) : 0.f;
        As[lk + 3][lr] = rok ? ((xa.w - mu) * rs * ga.w + ba.w) : 0.f;
        float4 wb = *(const float4*)(w + (size_t)(e0 + lr) * Dc + k0 + lk);
        Bs[lk + 0][lr] = wb.x;
        Bs[lk + 1][lr] = wb.y;
        Bs[lk + 2][lr] = wb.z;
        Bs[lk + 3][lr] = wb.w;
        __syncthreads();
        #pragma unroll
        for (int kk = 0; kk < 8; kk++) {
            float a[8], b[8];
            *(float4*)&a[0] = *(const float4*)&As[kk][trow];
            *(float4*)&a[4] = *(const float4*)&As[kk][trow + 4];
            *(float4*)&b[0] = *(const float4*)&Bs[kk][tcol];
            *(float4*)&b[4] = *(const float4*)&Bs[kk][tcol + 4];
            #pragma unroll
            for (int i = 0; i < 8; i++)
                #pragma unroll
                for (int j = 0; j < 8; j++) acc[i][j] += a[i] * b[j];
        }
        __syncthreads();
    }
    #pragma unroll
    for (int i = 0; i < 8; i++) {
        int m = m0 + trow + i;
        if (m < Mc) {
            float* cp = g_qkv + (size_t)m * E3c + e0 + tcol;
            *(float4*)cp       = *(float4*)&acc[i][0];
            *(float4*)(cp + 4) = *(float4*)&acc[i][4];
        }
    }
}

// ---------------- 3) RoPE + transpose to [B,H,N,64] --------------------------
__global__ void rope_k()
{
    const int TOT = Bc * Nc * Hc * 32;
    int idx = blockIdx.x * 256 + threadIdx.x;
    if (idx >= TOT) return;
    int j = idx & 31;                 // dim-pair index 0..31
    int h = (idx >> 5) % Hc;
    int t = idx / (32 * Hc);          // flat token 0..M-1
    int b = t / Nc;
    int n = t - b * Nc;
    int f = j & 15;                   // freq index within half
    int pos = 0;
    if (n != 0) {
        int p = n - 1;
        pos = (j < 16) ? (p >> 5) : (p & 31);   // row for first half, col for second
    }
    int d0 = (j < 16) ? (2 * f) : (32 + 2 * f);
    float inv = expf(-(float)f * 0.5756462732485114f);   // ln(10000)/16
    float ang = (float)pos * inv;
    float sn, cs;
    sincosf(ang, &sn, &cs);
    size_t src = (size_t)t * E3c + h * HDc + d0;
    float2 q2 = *(const float2*)(g_qkv + src);
    float2 k2 = *(const float2*)(g_qkv + src + Dc);
    float2 v2 = *(const float2*)(g_qkv + src + 2 * Dc);
    float2 qo, ko;
    qo.x = q2.x * cs - q2.y * sn;  qo.y = q2.y * cs + q2.x * sn;
    ko.x = k2.x * cs - k2.y * sn;  ko.y = k2.y * cs + k2.x * sn;
    size_t dst = (((size_t)(b * Hc + h)) * Nc + n) * HDc + d0;
    *(float2*)(g_q + dst) = qo;
    *(float2*)(g_k + dst) = ko;
    *(float2*)(g_v + dst) = v2;
}

// ---------------- 4) Flash attention, 64x64 tiles, fp32 ----------------------
__global__ __launch_bounds__(256) void attn_k()
{
    extern __shared__ float sm[];
    float* Qst = sm;                      // [64][68]  d-major (transposed)
    float* Kst = sm + 64 * QKPAD;         // [64][68]  d-major (transposed)
    float* Vs  = Kst + 64 * QKPAD;        // [64][64]  k-major
    float* Ps  = Vs + 64 * 64;            // [64][64]  q-major

    const int tid = threadIdx.x;
    const int bh = blockIdx.x;
    const int q0 = blockIdx.y * 64;
    const float* Qp = g_q + (size_t)bh * Nc * HDc;
    const float* Kp = g_k + (size_t)bh * Nc * HDc;
    const float* Vp = g_v + (size_t)bh * Nc * HDc;
    const int trow = (tid >> 4) * 4;
    const int tcol = (tid & 15) * 4;

    // load Q tile transposed, pre-scaled by hd^-0.5 = 1/8
    #pragma unroll
    for (int it = 0; it < 4; it++) {
        int i4 = tid + it * 256;
        int r = i4 >> 4;
        int c = (i4 & 15) * 4;
        int qr = q0 + r;
        float4 v = make_float4(0.f, 0.f, 0.f, 0.f);
        if (qr < Nc) v = *(const float4*)(Qp + (size_t)qr * HDc + c);
        Qst[(c + 0) * QKPAD + r] = v.x * 0.125f;
        Qst[(c + 1) * QKPAD + r] = v.y * 0.125f;
        Qst[(c + 2) * QKPAD + r] = v.z * 0.125f;
        Qst[(c + 3) * QKPAD + r] = v.w * 0.125f;
    }

    float m[4], l[4], o[4][4];
    #pragma unroll
    for (int i = 0; i < 4; i++) {
        m[i] = -1e30f; l[i] = 0.f;
        #pragma unroll
        for (int j = 0; j < 4; j++) o[i][j] = 0.f;
    }

    const int NT = (Nc + 63) / 64;    // 17
    for (int kt = 0; kt < NT; kt++) {
        const int k0 = kt * 64;
        __syncthreads();              // prev iter done with Vs/Ps
        #pragma unroll
        for (int it = 0; it < 4; it++) {
            int i4 = tid + it * 256;
            int r = i4 >> 4;
            int c = (i4 & 15) * 4;
            int kr = k0 + r;
            float4 kv = make_float4(0.f, 0.f, 0.f, 0.f);
            float4 vv = make_float4(0.f, 0.f, 0.f, 0.f);
            if (kr < Nc) {
                kv = *(const float4*)(Kp + (size_t)kr * HDc + c);
                vv = *(const float4*)(Vp + (size_t)kr * HDc + c);
            }
            Kst[(c + 0) * QKPAD + r] = kv.x;
            Kst[(c + 1) * QKPAD + r] = kv.y;
            Kst[(c + 2) * QKPAD + r] = kv.z;
            Kst[(c + 3) * QKPAD + r] = kv.w;
            *(float4*)(Vs + r * 64 + c) = vv;
        }
        __syncthreads();

        // S = (Q*scale) @ K^T  -> 4x4 per thread
        float s[4][4];
        #pragma unroll
        for (int i = 0; i < 4; i++)
            #pragma unroll
            for (int j = 0; j < 4; j++) s[i][j] = 0.f;
        #pragma unroll 8
        for (int d = 0; d < HDc; d++) {
            float4 a = *(const float4*)(Qst + d * QKPAD + trow);
            float4 b = *(const float4*)(Kst + d * QKPAD + tcol);
            float av[4] = {a.x, a.y, a.z, a.w};
            float bv[4] = {b.x, b.y, b.z, b.w};
            #pragma unroll
            for (int i = 0; i < 4; i++)
                #pragma unroll
                for (int j = 0; j < 4; j++) s[i][j] += av[i] * bv[j];
        }
        // mask out-of-range keys
        #pragma unroll
        for (int j = 0; j < 4; j++)
            if (k0 + tcol + j >= Nc) {
                #pragma unroll
                for (int i = 0; i < 4; i++) s[i][j] = -1e30f;
            }
        // online softmax (row owned by 16 lanes)
        #pragma unroll
        for (int i = 0; i < 4; i++) {
            float mx = fmaxf(fmaxf(s[i][0], s[i][1]), fmaxf(s[i][2], s[i][3]));
            #pragma unroll
            for (int off = 8; off; off >>= 1)
                mx = fmaxf(mx, __shfl_xor_sync(0xffffffffu, mx, off, 16));
            float mn = fmaxf(m[i], mx);
            float corr = __expf(m[i] - mn);
            float rsum = 0.f;
            #pragma unroll
            for (int j = 0; j < 4; j++) {
                float p = __expf(s[i][j] - mn);
                s[i][j] = p; rsum += p;
            }
            #pragma unroll
            for (int off = 8; off; off >>= 1)
                rsum += __shfl_xor_sync(0xffffffffu, rsum, off, 16);
            l[i] = l[i] * corr + rsum;
            m[i] = mn;
            #pragma unroll
            for (int j = 0; j < 4; j++) o[i][j] *= corr;
        }
        // publish P
        #pragma unroll
        for (int i = 0; i < 4; i++)
            *(float4*)(Ps + (trow + i) * 64 + tcol) = *(float4*)&s[i][0];
        __syncthreads();
        // O += P @ V
        for (int k = 0; k < 64; k += 4) {
            float pr[4][4];
            #pragma unroll
            for (int i = 0; i < 4; i++)
                *(float4*)&pr[i][0] = *(const float4*)(Ps + (trow + i) * 64 + k);
            #pragma unroll
            for (int kk = 0; kk < 4; kk++) {
                float4 bv = *(const float4*)(Vs + (k + kk) * 64 + tcol);
                #pragma unroll
                for (int i = 0; i < 4; i++) {
                    o[i][0] += pr[i][kk] * bv.x;
                    o[i][1] += pr[i][kk] * bv.y;
                    o[i][2] += pr[i][kk] * bv.z;
                    o[i][3] += pr[i][kk] * bv.w;
                }
            }
        }
    }
    // normalize + store
    #pragma unroll
    for (int i = 0; i < 4; i++) {
        int qr = q0 + trow + i;
        if (qr < Nc) {
            float inv = 1.f / l[i];
            float4 r4 = make_float4(o[i][0] * inv, o[i][1] * inv,
                                    o[i][2] * inv, o[i][3] * inv);
            *(float4*)(g_o + (size_t)bh * Nc * HDc + (size_t)qr * HDc + tcol) = r4;
        }
    }
}

// ---------------- 5) Output projection GEMM (+bias) --------------------------
// out[m, e] = sum_k O[b,h,n,d] * w_proj[e, k] + b_proj[e],  k = h*64+d
__global__ __launch_bounds__(256) void gemm_proj_k(
    const float* __restrict__ w, const float* __restrict__ bias,
    float* __restrict__ out)
{
    __shared__ float As[8][128];
    __shared__ float Bs[8][128];
    const int tid = threadIdx.x;
    const int m0 = blockIdx.y * 128;
    const int e0 = blockIdx.x * 128;
    const int lr = tid >> 1;
    const int lk = (tid & 1) * 4;
    const int row = m0 + lr;
    const bool rok = row < Mc;
    int bb = 0, nn = 0;
    if (rok) { bb = row / Nc; nn = row - bb * Nc; }
    const int trow = (tid >> 4) * 8;
    const int tcol = (tid & 15) * 8;
    float acc[8][8];
    #pragma unroll
    for (int i = 0; i < 8; i++)
        #pragma unroll
        for (int j = 0; j < 8; j++) acc[i][j] = 0.f;

    for (int k0 = 0; k0 < Dc; k0 += 8) {
        int k = k0 + lk;
        int h = k >> 6, d = k & 63;
        float4 xa = make_float4(0.f, 0.f, 0.f, 0.f);
        if (rok)
            xa = *(const float4*)(g_o + (((size_t)(bb * Hc + h)) * Nc + nn) * HDc + d);
        As[lk + 0][lr] = xa.x;
        As[lk + 1][lr] = xa.y;
        As[lk + 2][lr] = xa.z;
        As[lk + 3][lr] = xa.w;
        float4 wb = *(const float4*)(w + (size_t)(e0 + lr) * Dc + k0 + lk);
        Bs[lk + 0][lr] = wb.x;
        Bs[lk + 1][lr] = wb.y;
        Bs[lk + 2][lr] = wb.z;
        Bs[lk + 3][lr] = wb.w;
        __syncthreads();
        #pragma unroll
        for (int kk = 0; kk < 8; kk++) {
            float a[8], b[8];
            *(float4*)&a[0] = *(const float4*)&As[kk][trow];
            *(float4*)&a[4] = *(const float4*)&As[kk][trow + 4];
            *(float4*)&b[0] = *(const float4*)&Bs[kk][tcol];
            *(float4*)&b[4] = *(const float4*)&Bs[kk][tcol + 4];
            #pragma unroll
            for (int i = 0; i < 8; i++)
                #pragma unroll
                for (int j = 0; j < 8; j++) acc[i][j] += a[i] * b[j];
        }
        __syncthreads();
    }
    float4 bz0 = *(const float4*)(bias + e0 + tcol);
    float4 bz1 = *(const float4*)(bias + e0 + tcol + 4);
    #pragma unroll
    for (int i = 0; i < 8; i++) {
        int mm = m0 + trow + i;
        if (mm < Mc) {
            float4 c0 = make_float4(acc[i][0] + bz0.x, acc[i][1] + bz0.y,
                                    acc[i][2] + bz0.z, acc[i][3] + bz0.w);
            float4 c1 = make_float4(acc[i][4] + bz1.x, acc[i][5] + bz1.y,
                                    acc[i][6] + bz1.z, acc[i][7] + bz1.w);
            float* cp = out + (size_t)mm * Dc + e0 + tcol;
            *(float4*)cp       = c0;
            *(float4*)(cp + 4) = c1;
        }
    }
}

// ---------------- launch ------------------------------------------------------
extern "C" void kernel_launch(void* const* d_in, const int* in_sizes, int n_in,
                              void* d_out, int out_size)
{
    const float* x  = (const float*)d_in[0];
    const float* lg = (const float*)d_in[1];
    const float* lb = (const float*)d_in[2];
    const float* wq = (const float*)d_in[3];
    const float* wp = (const float*)d_in[4];
    const float* bp = (const float*)d_in[5];
    float* out = (float*)d_out;
    (void)in_sizes; (void)n_in; (void)out_size;

    cudaFuncSetAttribute(attn_k, cudaFuncAttributeMaxDynamicSharedMemorySize,
                         ATTN_SMEM);

    ln_stats_k<<<Mc, 256>>>(x);
    gemm_qkv_k<<<dim3(E3c / 128, (Mc + 127) / 128), 256>>>(x, lg, lb, wq);
    rope_k<<<(Bc * Nc * Hc * 32 + 255) / 256, 256>>>();
    attn_k<<<dim3(Bc * Hc, (Nc + 63) / 64), 256, ATTN_SMEM>>>();
    gemm_proj_k<<<dim3(Dc / 128, (Mc + 127) / 128), 256>>>(wp, bp, out);
}

// round 6
// speedup vs baseline: 1.0045x; 1.0045x over previous
#include <cuda_runtime.h>
#include <math.h>

#define Bc   8
#define Nc   1025
#define Dc   768
#define Hc   12
#define HDc  64
#define E3c  2304
#define Mc   (Bc*Nc)      // 8200
#define QKPAD 68
#define ATTN_SMEM ((64*QKPAD*2 + 64*64*2)*4)   // Qst + Kst + Vs + Ps = 67584 B

// ---------------- scratch (static device globals; no runtime alloc) ----------
__device__ float g_mu [Mc];
__device__ float g_rs [Mc];
__device__ float g_qkv[(size_t)Mc * E3c];                 // [M][3][H][64]
__device__ float g_q  [(size_t)Bc * Hc * Nc * HDc];       // [B][H][N][64]
__device__ float g_k  [(size_t)Bc * Hc * Nc * HDc];
__device__ float g_v  [(size_t)Bc * Hc * Nc * HDc];
__device__ float g_o  [(size_t)Bc * Hc * Nc * HDc];

// ---------------- 1) LayerNorm row stats ------------------------------------
__global__ __launch_bounds__(256) void ln_stats_k(const float* __restrict__ x)
{
    const int row = blockIdx.x;
    const float* xr = x + (size_t)row * Dc;
    float s = 0.f, s2 = 0.f;
    for (int i = threadIdx.x; i < Dc; i += 256) {
        float v = xr[i];
        s += v; s2 += v * v;
    }
    #pragma unroll
    for (int o = 16; o; o >>= 1) {
        s  += __shfl_xor_sync(0xffffffffu, s,  o);
        s2 += __shfl_xor_sync(0xffffffffu, s2, o);
    }
    __shared__ float sh[16];
    const int w = threadIdx.x >> 5;
    if ((threadIdx.x & 31) == 0) { sh[w] = s; sh[8 + w] = s2; }
    __syncthreads();
    if (threadIdx.x < 32) {
        s  = (threadIdx.x < 8) ? sh[threadIdx.x]     : 0.f;
        s2 = (threadIdx.x < 8) ? sh[8 + threadIdx.x] : 0.f;
        #pragma unroll
        for (int o = 4; o; o >>= 1) {
            s  += __shfl_xor_sync(0xffffffffu, s,  o);
            s2 += __shfl_xor_sync(0xffffffffu, s2, o);
        }
        if (threadIdx.x == 0) {
            float mu  = s  * (1.f / Dc);
            float var = s2 * (1.f / Dc) - mu * mu;
            g_mu[row] = mu;
            g_rs[row] = rsqrtf(var + 1e-5f);
        }
    }
}

// ---------------- 2) QKV GEMM (LN fused into A loads) ------------------------
// C[m, e] = sum_d LN(x)[m,d] * w_qkv[e,d]       (M=8200, E=2304, K=768)
__global__ __launch_bounds__(256) void gemm_qkv_k(
    const float* __restrict__ x,  const float* __restrict__ lg,
    const float* __restrict__ lb, const float* __restrict__ w)
{
    __shared__ float As[8][128];
    __shared__ float Bs[8][128];
    const int tid = threadIdx.x;
    const int m0 = blockIdx.y * 128;
    const int e0 = blockIdx.x * 128;
    const int lr = tid >> 1;
    const int lk = (tid & 1) * 4;
    const int row = m0 + lr;
    const bool rok = row < Mc;
    const float mu = rok ? g_mu[row] : 0.f;
    const float rs = rok ? g_rs[row] : 0.f;
    const int trow = (tid >> 4) * 8;
    const int tcol = (tid & 15) * 8;
    float acc[8][8];
    #pragma unroll
    for (int i = 0; i < 8; i++)
        #pragma unroll
        for (int j = 0; j < 8; j++) acc[i][j] = 0.f;

    for (int k0 = 0; k0 < Dc; k0 += 8) {
        float4 xa = make_float4(0.f, 0.f, 0.f, 0.f);
        if (rok) xa = *(const float4*)(x + (size_t)row * Dc + k0 + lk);
        float4 ga = *(const float4*)(lg + k0 + lk);
        float4 ba = *(const float4*)(lb + k0 + lk);
        As[lk + 0][lr] = rok ? ((xa.x - mu) * rs * ga.x + ba.x) : 0.f;
        As[lk + 1][lr] = rok ? ((xa.y - mu) * rs * ga.y + ba.y) : 0.f;
        As[lk + 2][lr] = rok ? ((xa.z - mu) * rs * ga.z + ba.z) : 0.f;
        As[lk + 3][lr] = rok ? ((xa.w - mu) * rs * ga.w + ba.w) : 0.f;
        float4 wb = *(const float4*)(w + (size_t)(e0 + lr) * Dc + k0 + lk);
        Bs[lk + 0][lr] = wb.x;
        Bs[lk + 1][lr] = wb.y;
        Bs[lk + 2][lr] = wb.z;
        Bs[lk + 3][lr] = wb.w;
        __syncthreads();
        #pragma unroll
        for (int kk = 0; kk < 8; kk++) {
            float a[8], b[8];
            *(float4*)&a[0] = *(const float4*)&As[kk][trow];
            *(float4*)&a[4] = *(const float4*)&As[kk][trow + 4];
            *(float4*)&b[0] = *(const float4*)&Bs[kk][tcol];
            *(float4*)&b[4] = *(const float4*)&Bs[kk][tcol + 4];
            #pragma unroll
            for (int i = 0; i < 8; i++)
                #pragma unroll
                for (int j = 0; j < 8; j++) acc[i][j] += a[i] * b[j];
        }
        __syncthreads();
    }
    #pragma unroll
    for (int i = 0; i < 8; i++) {
        int m = m0 + trow + i;
        if (m < Mc) {
            float* cp = g_qkv + (size_t)m * E3c + e0 + tcol;
            *(float4*)cp       = *(float4*)&acc[i][0];
            *(float4*)(cp + 4) = *(float4*)&acc[i][4];
        }
    }
}

// ---------------- 3) RoPE + transpose to [B,H,N,64] --------------------------
__global__ void rope_k()
{
    const int TOT = Bc * Nc * Hc * 32;
    int idx = blockIdx.x * 256 + threadIdx.x;
    if (idx >= TOT) return;
    int j = idx & 31;                 // dim-pair index 0..31
    int h = (idx >> 5) % Hc;
    int t = idx / (32 * Hc);          // flat token 0..M-1
    int b = t / Nc;
    int n = t - b * Nc;
    int f = j & 15;                   // freq index within half
    int pos = 0;
    if (n != 0) {
        int p = n - 1;
        pos = (j < 16) ? (p >> 5) : (p & 31);   // row for first half, col for second
    }
    int d0 = (j < 16) ? (2 * f) : (32 + 2 * f);
    float inv = expf(-(float)f * 0.5756462732485114f);   // ln(10000)/16
    float ang = (float)pos * inv;
    float sn, cs;
    sincosf(ang, &sn, &cs);
    size_t src = (size_t)t * E3c + h * HDc + d0;
    float2 q2 = *(const float2*)(g_qkv + src);
    float2 k2 = *(const float2*)(g_qkv + src + Dc);
    float2 v2 = *(const float2*)(g_qkv + src + 2 * Dc);
    float2 qo, ko;
    qo.x = q2.x * cs - q2.y * sn;  qo.y = q2.y * cs + q2.x * sn;
    ko.x = k2.x * cs - k2.y * sn;  ko.y = k2.y * cs + k2.x * sn;
    size_t dst = (((size_t)(b * Hc + h)) * Nc + n) * HDc + d0;
    *(float2*)(g_q + dst) = qo;
    *(float2*)(g_k + dst) = ko;
    *(float2*)(g_v + dst) = v2;
}

// ---------------- 4) Flash attention, 64x64 tiles, fp32 ----------------------
__global__ __launch_bounds__(256) void attn_k()
{
    extern __shared__ float sm[];
    float* Qst = sm;                      // [64][68]  d-major (transposed)
    float* Kst = sm + 64 * QKPAD;         // [64][68]  d-major (transposed)
    float* Vs  = Kst + 64 * QKPAD;        // [64][64]  k-major
    float* Ps  = Vs + 64 * 64;            // [64][64]  q-major

    const int tid = threadIdx.x;
    const int bh = blockIdx.x;
    const int q0 = blockIdx.y * 64;
    const float* Qp = g_q + (size_t)bh * Nc * HDc;
    const float* Kp = g_k + (size_t)bh * Nc * HDc;
    const float* Vp = g_v + (size_t)bh * Nc * HDc;
    const int trow = (tid >> 4) * 4;
    const int tcol = (tid & 15) * 4;

    // load Q tile transposed, pre-scaled by hd^-0.5 = 1/8
    #pragma unroll
    for (int it = 0; it < 4; it++) {
        int i4 = tid + it * 256;
        int r = i4 >> 4;
        int c = (i4 & 15) * 4;
        int qr = q0 + r;
        float4 v = make_float4(0.f, 0.f, 0.f, 0.f);
        if (qr < Nc) v = *(const float4*)(Qp + (size_t)qr * HDc + c);
        Qst[(c + 0) * QKPAD + r] = v.x * 0.125f;
        Qst[(c + 1) * QKPAD + r] = v.y * 0.125f;
        Qst[(c + 2) * QKPAD + r] = v.z * 0.125f;
        Qst[(c + 3) * QKPAD + r] = v.w * 0.125f;
    }

    float m[4], l[4], o[4][4];
    #pragma unroll
    for (int i = 0; i < 4; i++) {
        m[i] = -1e30f; l[i] = 0.f;
        #pragma unroll
        for (int j = 0; j < 4; j++) o[i][j] = 0.f;
    }

    const int NT = (Nc + 63) / 64;    // 17
    for (int kt = 0; kt < NT; kt++) {
        const int k0 = kt * 64;
        __syncthreads();              // prev iter done with Vs/Ps
        #pragma unroll
        for (int it = 0; it < 4; it++) {
            int i4 = tid + it * 256;
            int r = i4 >> 4;
            int c = (i4 & 15) * 4;
            int kr = k0 + r;
            float4 kv = make_float4(0.f, 0.f, 0.f, 0.f);
            float4 vv = make_float4(0.f, 0.f, 0.f, 0.f);
            if (kr < Nc) {
                kv = *(const float4*)(Kp + (size_t)kr * HDc + c);
                vv = *(const float4*)(Vp + (size_t)kr * HDc + c);
            }
            Kst[(c + 0) * QKPAD + r] = kv.x;
            Kst[(c + 1) * QKPAD + r] = kv.y;
            Kst[(c + 2) * QKPAD + r] = kv.z;
            Kst[(c + 3) * QKPAD + r] = kv.w;
            *(float4*)(Vs + r * 64 + c) = vv;
        }
        __syncthreads();

        // S = (Q*scale) @ K^T  -> 4x4 per thread
        float s[4][4];
        #pragma unroll
        for (int i = 0; i < 4; i++)
            #pragma unroll
            for (int j = 0; j < 4; j++) s[i][j] = 0.f;
        #pragma unroll 8
        for (int d = 0; d < HDc; d++) {
            float4 a = *(const float4*)(Qst + d * QKPAD + trow);
            float4 b = *(const float4*)(Kst + d * QKPAD + tcol);
            float av[4] = {a.x, a.y, a.z, a.w};
            float bv[4] = {b.x, b.y, b.z, b.w};
            #pragma unroll
            for (int i = 0; i < 4; i++)
                #pragma unroll
                for (int j = 0; j < 4; j++) s[i][j] += av[i] * bv[j];
        }
        // mask out-of-range keys
        #pragma unroll
        for (int j = 0; j < 4; j++)
            if (k0 + tcol + j >= Nc) {
                #pragma unroll
                for (int i = 0; i < 4; i++) s[i][j] = -1e30f;
            }
        // online softmax (row owned by 16 lanes)
        #pragma unroll
        for (int i = 0; i < 4; i++) {
            float mx = fmaxf(fmaxf(s[i][0], s[i][1]), fmaxf(s[i][2], s[i][3]));
            #pragma unroll
            for (int off = 8; off; off >>= 1)
                mx = fmaxf(mx, __shfl_xor_sync(0xffffffffu, mx, off, 16));
            float mn = fmaxf(m[i], mx);
            float corr = __expf(m[i] - mn);
            float rsum = 0.f;
            #pragma unroll
            for (int j = 0; j < 4; j++) {
                float p = __expf(s[i][j] - mn);
                s[i][j] = p; rsum += p;
            }
            #pragma unroll
            for (int off = 8; off; off >>= 1)
                rsum += __shfl_xor_sync(0xffffffffu, rsum, off, 16);
            l[i] = l[i] * corr + rsum;
            m[i] = mn;
            #pragma unroll
            for (int j = 0; j < 4; j++) o[i][j] *= corr;
        }
        // publish P
        #pragma unroll
        for (int i = 0; i < 4; i++)
            *(float4*)(Ps + (trow + i) * 64 + tcol) = *(float4*)&s[i][0];
        __syncthreads();
        // O += P @ V
        for (int k = 0; k < 64; k += 4) {
            float pr[4][4];
            #pragma unroll
            for (int i = 0; i < 4; i++)
                *(float4*)&pr[i][0] = *(const float4*)(Ps + (trow + i) * 64 + k);
            #pragma unroll
            for (int kk = 0; kk < 4; kk++) {
                float4 bv = *(const float4*)(Vs + (k + kk) * 64 + tcol);
                #pragma unroll
                for (int i = 0; i < 4; i++) {
                    o[i][0] += pr[i][kk] * bv.x;
                    o[i][1] += pr[i][kk] * bv.y;
                    o[i][2] += pr[i][kk] * bv.z;
                    o[i][3] += pr[i][kk] * bv.w;
                }
            }
        }
    }
    // normalize + store
    #pragma unroll
    for (int i = 0; i < 4; i++) {
        int qr = q0 + trow + i;
        if (qr < Nc) {
            float inv = 1.f / l[i];
            float4 r4 = make_float4(o[i][0] * inv, o[i][1] * inv,
                                    o[i][2] * inv, o[i][3] * inv);
            *(float4*)(g_o + (size_t)bh * Nc * HDc + (size_t)qr * HDc + tcol) = r4;
        }
    }
}

// ---------------- 5) Output projection GEMM (+bias) --------------------------
// out[m, e] = sum_k O[b,h,n,d] * w_proj[e, k] + b_proj[e],  k = h*64+d
__global__ __launch_bounds__(256) void gemm_proj_k(
    const float* __restrict__ w, const float* __restrict__ bias,
    float* __restrict__ out)
{
    __shared__ float As[8][128];
    __shared__ float Bs[8][128];
    const int tid = threadIdx.x;
    const int m0 = blockIdx.y * 128;
    const int e0 = blockIdx.x * 128;
    const int lr = tid >> 1;
    const int lk = (tid & 1) * 4;
    const int row = m0 + lr;
    const bool rok = row < Mc;
    int bb = 0, nn = 0;
    if (rok) { bb = row / Nc; nn = row - bb * Nc; }
    const int trow = (tid >> 4) * 8;
    const int tcol = (tid & 15) * 8;
    float acc[8][8];
    #pragma unroll
    for (int i = 0; i < 8; i++)
        #pragma unroll
        for (int j = 0; j < 8; j++) acc[i][j] = 0.f;

    for (int k0 = 0; k0 < Dc; k0 += 8) {
        int k = k0 + lk;
        int h = k >> 6, d = k & 63;
        float4 xa = make_float4(0.f, 0.f, 0.f, 0.f);
        if (rok)
            xa = *(const float4*)(g_o + (((size_t)(bb * Hc + h)) * Nc + nn) * HDc + d);
        As[lk + 0][lr] = xa.x;
        As[lk + 1][lr] = xa.y;
        As[lk + 2][lr] = xa.z;
        As[lk + 3][lr] = xa.w;
        float4 wb = *(const float4*)(w + (size_t)(e0 + lr) * Dc + k0 + lk);
        Bs[lk + 0][lr] = wb.x;
        Bs[lk + 1][lr] = wb.y;
        Bs[lk + 2][lr] = wb.z;
        Bs[lk + 3][lr] = wb.w;
        __syncthreads();
        #pragma unroll
        for (int kk = 0; kk < 8; kk++) {
            float a[8], b[8];
            *(float4*)&a[0] = *(const float4*)&As[kk][trow];
            *(float4*)&a[4] = *(const float4*)&As[kk][trow + 4];
            *(float4*)&b[0] = *(const float4*)&Bs[kk][tcol];
            *(float4*)&b[4] = *(const float4*)&Bs[kk][tcol + 4];
            #pragma unroll
            for (int i = 0; i < 8; i++)
                #pragma unroll
                for (int j = 0; j < 8; j++) acc[i][j] += a[i] * b[j];
        }
        __syncthreads();
    }
    float4 bz0 = *(const float4*)(bias + e0 + tcol);
    float4 bz1 = *(const float4*)(bias + e0 + tcol + 4);
    #pragma unroll
    for (int i = 0; i < 8; i++) {
        int mm = m0 + trow + i;
        if (mm < Mc) {
            float4 c0 = make_float4(acc[i][0] + bz0.x, acc[i][1] + bz0.y,
                                    acc[i][2] + bz0.z, acc[i][3] + bz0.w);
            float4 c1 = make_float4(acc[i][4] + bz1.x, acc[i][5] + bz1.y,
                                    acc[i][6] + bz1.z, acc[i][7] + bz1.w);
            float* cp = out + (size_t)mm * Dc + e0 + tcol;
            *(float4*)cp       = c0;
            *(float4*)(cp + 4) = c1;
        }
    }
}

// ---------------- launch ------------------------------------------------------
extern "C" void kernel_launch(void* const* d_in, const int* in_sizes, int n_in,
                              void* d_out, int out_size)
{
    const float* x  = (const float*)d_in[0];
    const float* lg = (const float*)d_in[1];
    const float* lb = (const float*)d_in[2];
    const float* wq = (const float*)d_in[3];
    const float* wp = (const float*)d_in[4];
    const float* bp = (const float*)d_in[5];
    float* out = (float*)d_out;
    (void)in_sizes; (void)n_in; (void)out_size;

    cudaFuncSetAttribute(attn_k, cudaFuncAttributeMaxDynamicSharedMemorySize,
                         ATTN_SMEM);

    ln_stats_k<<<Mc, 256>>>(x);
    gemm_qkv_k<<<dim3(E3c / 128, (Mc + 127) / 128), 256>>>(x, lg, lb, wq);
    rope_k<<<(Bc * Nc * Hc * 32 + 255) / 256, 256>>>();
    attn_k<<<dim3(Bc * Hc, (Nc + 63) / 64), 256, ATTN_SMEM>>>();
    gemm_proj_k<<<dim3(Dc / 128, (Mc + 127) / 128), 256>>>(wp, bp, out);
}

// round 8
// speedup vs baseline: 1.4254x; 1.4190x over previous
#include <cuda_runtime.h>
#include <cuda_bf16.h>
#include <cstdint>
#include <math.h>

#define Bc   8
#define Nc   1025
#define Dc   768
#define Hc   12
#define HDc  64
#define E3c  2304
#define Mc   (Bc*Nc)      // 8200
#define MP   8320         // M padded to 65*128
#define QKPAD 68
#define ATTN_SMEM ((64*QKPAD*2 + 64*64*2)*4)   // 67584 B

// ---- mma.sync gemm config ----
#define BM 128
#define BN 128
#define BK 32
#define NK (Dc/BK)              // 24
#define ROWB 80                 // padded row pitch bytes (32 bf16 = 64B + 16B pad)
#define ARR_BYTES (128*ROWB)    // 10240 per operand array
#define STAGE_BYTES (4*ARR_BYTES) // Ah, Al, Bh, Bl = 40960
#define GEMM_SMEM (2*STAGE_BYTES) // 81920

// ---------------- scratch ----------------
__device__ float g_mu [Mc];
__device__ float g_rs [Mc];
__device__ float g_qkv[(size_t)Mc * E3c];
__device__ float g_q  [(size_t)Bc * Hc * Nc * HDc];
__device__ float g_k  [(size_t)Bc * Hc * Nc * HDc];
__device__ float g_v  [(size_t)Bc * Hc * Nc * HDc];
__device__ float g_o  [(size_t)Bc * Hc * Nc * HDc];
// bf16 hi/lo split operands
__device__ __nv_bfloat16 g_ahi[(size_t)MP * Dc];
__device__ __nv_bfloat16 g_alo[(size_t)MP * Dc];
__device__ __nv_bfloat16 g_ohi[(size_t)MP * Dc];
__device__ __nv_bfloat16 g_olo[(size_t)MP * Dc];
__device__ __nv_bfloat16 g_wqhi[(size_t)E3c * Dc];
__device__ __nv_bfloat16 g_wqlo[(size_t)E3c * Dc];
__device__ __nv_bfloat16 g_wphi[(size_t)Dc * Dc];
__device__ __nv_bfloat16 g_wplo[(size_t)Dc * Dc];

// ================= helpers =================
__device__ __forceinline__ uint32_t smem_u32(const void* p) {
    uint32_t a;
    asm("{ .reg .u64 t; cvta.to.shared.u64 t, %1; cvt.u32.u64 %0, t; }"
        : "=r"(a) : "l"(p));
    return a;
}

#define LDM4(r0, r1, r2, r3, addr) \
    asm volatile("ldmatrix.sync.aligned.m8n8.x4.shared.b16 {%0,%1,%2,%3}, [%4];" \
        : "=r"(r0), "=r"(r1), "=r"(r2), "=r"(r3) : "r"(addr))

#define MMA16816(d, a, b0, b1) \
    asm volatile("mma.sync.aligned.m16n8k16.row.col.f32.bf16.bf16.f32 " \
        "{%0,%1,%2,%3}, {%4,%5,%6,%7}, {%8,%9}, {%0,%1,%2,%3};" \
        : "+f"((d)[0]), "+f"((d)[1]), "+f"((d)[2]), "+f"((d)[3]) \
        : "r"((a)[0]), "r"((a)[1]), "r"((a)[2]), "r"((a)[3]), "r"(b0), "r"(b1))

__device__ __forceinline__ void cp16(uint32_t dst, const void* src) {
    asm volatile("cp.async.cg.shared.global [%0], [%1], 16;" ::
        "r"(dst), "l"(src));
}
__device__ __forceinline__ void cp_commit() {
    asm volatile("cp.async.commit_group;" ::: "memory");
}
template<int N>
__device__ __forceinline__ void cp_wait() {
    asm volatile("cp.async.wait_group %0;" :: "n"(N) : "memory");
}

// ---------------- 1) LayerNorm row stats ------------------------------------
__global__ __launch_bounds__(256) void ln_stats_k(const float* __restrict__ x)
{
    const int row = blockIdx.x;
    const float* xr = x + (size_t)row * Dc;
    float s = 0.f, s2 = 0.f;
    for (int i = threadIdx.x; i < Dc; i += 256) {
        float v = xr[i];
        s += v; s2 += v * v;
    }
    #pragma unroll
    for (int o = 16; o; o >>= 1) {
        s  += __shfl_xor_sync(0xffffffffu, s,  o);
        s2 += __shfl_xor_sync(0xffffffffu, s2, o);
    }
    __shared__ float sh[16];
    const int w = threadIdx.x >> 5;
    if ((threadIdx.x & 31) == 0) { sh[w] = s; sh[8 + w] = s2; }
    __syncthreads();
    if (threadIdx.x < 32) {
        s  = (threadIdx.x < 8) ? sh[threadIdx.x]     : 0.f;
        s2 = (threadIdx.x < 8) ? sh[8 + threadIdx.x] : 0.f;
        #pragma unroll
        for (int o = 4; o; o >>= 1) {
            s  += __shfl_xor_sync(0xffffffffu, s,  o);
            s2 += __shfl_xor_sync(0xffffffffu, s2, o);
        }
        if (threadIdx.x == 0) {
            float mu  = s  * (1.f / Dc);
            float var = s2 * (1.f / Dc) - mu * mu;
            g_mu[row] = mu;
            g_rs[row] = rsqrtf(var + 1e-5f);
        }
    }
}

// ---------------- split helpers ----------------------------------------------
__device__ __forceinline__ void split_bf16(float v, __nv_bfloat16& h, __nv_bfloat16& l) {
    h = __float2bfloat16(v);
    l = __float2bfloat16(v - __bfloat162float(h));
}

__global__ __launch_bounds__(256) void split_ln_k(
    const float* __restrict__ x, const float* __restrict__ lg, const float* __restrict__ lb)
{
    const int m = blockIdx.x;
    const bool ok = m < Mc;
    const float mu = ok ? g_mu[m] : 0.f;
    const float rs = ok ? g_rs[m] : 0.f;
    for (int c = threadIdx.x; c < Dc; c += 256) {
        float v = 0.f;
        if (ok) v = (x[(size_t)m * Dc + c] - mu) * rs * lg[c] + lb[c];
        __nv_bfloat16 h, l;
        split_bf16(v, h, l);
        g_ahi[(size_t)m * Dc + c] = h;
        g_alo[(size_t)m * Dc + c] = l;
    }
}

template<int WHICH>
__global__ void split_w_k(const float* __restrict__ w, int n)
{
    int i = blockIdx.x * 256 + threadIdx.x;
    if (i >= n) return;
    __nv_bfloat16 h, l;
    split_bf16(w[i], h, l);
    if (WHICH == 0) { g_wqhi[i] = h; g_wqlo[i] = l; }
    else            { g_wphi[i] = h; g_wplo[i] = l; }
}

__global__ __launch_bounds__(256) void split_o_k()
{
    const int m = blockIdx.x;
    const bool ok = m < Mc;
    int bb = 0, nn = 0;
    if (ok) { bb = m / Nc; nn = m - bb * Nc; }
    for (int c = threadIdx.x; c < Dc; c += 256) {
        float v = 0.f;
        if (ok) {
            int h = c >> 6, d = c & 63;
            v = g_o[(((size_t)(bb * Hc + h)) * Nc + nn) * HDc + d];
        }
        __nv_bfloat16 hi, lo;
        split_bf16(v, hi, lo);
        g_ohi[(size_t)m * Dc + c] = hi;
        g_olo[(size_t)m * Dc + c] = lo;
    }
}

// ---------------- 2) mma.sync 3xBF16 GEMM ------------------------------------
// MODE 0: g_qkv[m][e] = A(LN) @ w_qkv^T              (E = 2304)
// MODE 1: out[m][e]  = A(attn-out) @ w_proj^T + bias (E = 768)
template<int MODE>
__global__ __launch_bounds__(256, 1) void mma_gemm_k(
    const float* __restrict__ bias, float* __restrict__ outp)
{
    constexpr int E = (MODE == 0) ? E3c : Dc;
    const __nv_bfloat16* __restrict__ Ahi = (MODE == 0) ? g_ahi : g_ohi;
    const __nv_bfloat16* __restrict__ Alo = (MODE == 0) ? g_alo : g_olo;
    const __nv_bfloat16* __restrict__ Bhi = (MODE == 0) ? g_wqhi : g_wphi;
    const __nv_bfloat16* __restrict__ Blo = (MODE == 0) ? g_wqlo : g_wplo;
    float* __restrict__ C = (MODE == 0) ? g_qkv : outp;

    extern __shared__ char smem[];
    const uint32_t sb = smem_u32(smem);
    const int tid  = threadIdx.x;
    const int wid  = tid >> 5;
    const int lane = tid & 31;
    const int wm = wid >> 2;            // 0..1  (64 rows each)
    const int wn = wid & 3;             // 0..3  (32 cols each)
    const int e0 = blockIdx.x * BN;
    const int m0 = blockIdx.y * BM;

    // per-array source base (row 0 of this block's slab)
    const __nv_bfloat16* gA[4] = {
        Ahi + (size_t)m0 * Dc, Alo + (size_t)m0 * Dc,
        Bhi + (size_t)e0 * Dc, Blo + (size_t)e0 * Dc };

    // ---- async stage loader: 8 x 16B per thread ----
    auto load_stage = [&](int s, int k0) {
        const uint32_t stg = sb + s * STAGE_BYTES;
        #pragma unroll
        for (int arr = 0; arr < 4; arr++) {
            #pragma unroll
            for (int i = 0; i < 2; i++) {
                int ci = tid + i * 256;          // 0..511
                int r = ci >> 2, c = ci & 3;
                cp16(stg + arr * ARR_BYTES + r * ROWB + c * 16,
                     gA[arr] + (size_t)r * Dc + k0 + c * 8);
            }
        }
        cp_commit();
    };

    float acc[4][4][4];
    #pragma unroll
    for (int i = 0; i < 4; i++)
        #pragma unroll
        for (int j = 0; j < 4; j++)
            #pragma unroll
            for (int q = 0; q < 4; q++) acc[i][j][q] = 0.f;

    // ldmatrix lane geometry
    const int a_row   = (lane & 7) + ((lane >> 3) & 1) * 8;   // within 16-row tile
    const int a_chunk = (lane >> 4) & 1;                       // +k16*2
    const int b_row   = (lane & 7) + ((lane >> 4) & 1) * 8;   // within 16-col (n) group
    const int b_chunk = (lane >> 3) & 1;

    load_stage(0, 0);

    for (int it = 0; it < NK; it++) {
        if (it + 1 < NK) load_stage((it + 1) & 1, (it + 1) * BK);
        if (it + 1 < NK) cp_wait<1>(); else cp_wait<0>();
        __syncthreads();

        const uint32_t stg = sb + (it & 1) * STAGE_BYTES;
        const uint32_t aHi = stg;
        const uint32_t aLo = stg + ARR_BYTES;
        const uint32_t bHi = stg + 2 * ARR_BYTES;
        const uint32_t bLo = stg + 3 * ARR_BYTES;

        #pragma unroll
        for (int k16 = 0; k16 < 2; k16++) {
            uint32_t ah[4][4], al[4][4], bh[2][4], bl[2][4];
            #pragma unroll
            for (int i = 0; i < 4; i++) {
                uint32_t ro = (uint32_t)((wm * 64 + i * 16 + a_row) * ROWB
                                         + (k16 * 2 + a_chunk) * 16);
                LDM4(ah[i][0], ah[i][1], ah[i][2], ah[i][3], aHi + ro);
                LDM4(al[i][0], al[i][1], al[i][2], al[i][3], aLo + ro);
            }
            #pragma unroll
            for (int j2 = 0; j2 < 2; j2++) {
                uint32_t ro = (uint32_t)((wn * 32 + j2 * 16 + b_row) * ROWB
                                         + (k16 * 2 + b_chunk) * 16);
                LDM4(bh[j2][0], bh[j2][1], bh[j2][2], bh[j2][3], bHi + ro);
                LDM4(bl[j2][0], bl[j2][1], bl[j2][2], bl[j2][3], bLo + ro);
            }
            #pragma unroll
            for (int i = 0; i < 4; i++) {
                #pragma unroll
                for (int j = 0; j < 4; j++) {
                    uint32_t h0 = bh[j >> 1][(j & 1) * 2];
                    uint32_t h1 = bh[j >> 1][(j & 1) * 2 + 1];
                    uint32_t l0 = bl[j >> 1][(j & 1) * 2];
                    uint32_t l1 = bl[j >> 1][(j & 1) * 2 + 1];
                    MMA16816(acc[i][j], ah[i], h0, h1);
                    MMA16816(acc[i][j], ah[i], l0, l1);
                    MMA16816(acc[i][j], al[i], h0, h1);
                }
            }
        }
        __syncthreads();
    }

    // ---- epilogue ----
    const int gid = lane >> 2, tig = lane & 3;
    #pragma unroll
    for (int i = 0; i < 4; i++) {
        #pragma unroll
        for (int j = 0; j < 4; j++) {
            int col  = e0 + wn * 32 + j * 8 + tig * 2;
            int row0 = m0 + wm * 64 + i * 16 + gid;
            int row1 = row0 + 8;
            float2 v0 = make_float2(acc[i][j][0], acc[i][j][1]);
            float2 v1 = make_float2(acc[i][j][2], acc[i][j][3]);
            if (MODE == 1) {
                float2 bz = *(const float2*)(bias + col);
                v0.x += bz.x; v0.y += bz.y;
                v1.x += bz.x; v1.y += bz.y;
            }
            if (row0 < Mc) *(float2*)(C + (size_t)row0 * E + col) = v0;
            if (row1 < Mc) *(float2*)(C + (size_t)row1 * E + col) = v1;
        }
    }
}

// ---------------- 3) RoPE + transpose to [B,H,N,64] --------------------------
__global__ void rope_k()
{
    const int TOT = Bc * Nc * Hc * 32;
    int idx = blockIdx.x * 256 + threadIdx.x;
    if (idx >= TOT) return;
    int j = idx & 31;
    int h = (idx >> 5) % Hc;
    int t = idx / (32 * Hc);
    int b = t / Nc;
    int n = t - b * Nc;
    int f = j & 15;
    int pos = 0;
    if (n != 0) {
        int p = n - 1;
        pos = (j < 16) ? (p >> 5) : (p & 31);
    }
    int d0 = (j < 16) ? (2 * f) : (32 + 2 * f);
    float inv = expf(-(float)f * 0.5756462732485114f);
    float ang = (float)pos * inv;
    float sn, cs;
    sincosf(ang, &sn, &cs);
    size_t src = (size_t)t * E3c + h * HDc + d0;
    float2 q2 = *(const float2*)(g_qkv + src);
    float2 k2 = *(const float2*)(g_qkv + src + Dc);
    float2 v2 = *(const float2*)(g_qkv + src + 2 * Dc);
    float2 qo, ko;
    qo.x = q2.x * cs - q2.y * sn;  qo.y = q2.y * cs + q2.x * sn;
    ko.x = k2.x * cs - k2.y * sn;  ko.y = k2.y * cs + k2.x * sn;
    size_t dst = (((size_t)(b * Hc + h)) * Nc + n) * HDc + d0;
    *(float2*)(g_q + dst) = qo;
    *(float2*)(g_k + dst) = ko;
    *(float2*)(g_v + dst) = v2;
}

// ---------------- 4) Flash attention, 64x64 tiles, fp32 ----------------------
__global__ __launch_bounds__(256) void attn_k()
{
    extern __shared__ float sm[];
    float* Qst = sm;
    float* Kst = sm + 64 * QKPAD;
    float* Vs  = Kst + 64 * QKPAD;
    float* Ps  = Vs + 64 * 64;

    const int tid = threadIdx.x;
    const int bh = blockIdx.x;
    const int q0 = blockIdx.y * 64;
    const float* Qp = g_q + (size_t)bh * Nc * HDc;
    const float* Kp = g_k + (size_t)bh * Nc * HDc;
    const float* Vp = g_v + (size_t)bh * Nc * HDc;
    const int trow = (tid >> 4) * 4;
    const int tcol = (tid & 15) * 4;

    #pragma unroll
    for (int it = 0; it < 4; it++) {
        int i4 = tid + it * 256;
        int r = i4 >> 4;
        int c = (i4 & 15) * 4;
        int qr = q0 + r;
        float4 v = make_float4(0.f, 0.f, 0.f, 0.f);
        if (qr < Nc) v = *(const float4*)(Qp + (size_t)qr * HDc + c);
        Qst[(c + 0) * QKPAD + r] = v.x * 0.125f;
        Qst[(c + 1) * QKPAD + r] = v.y * 0.125f;
        Qst[(c + 2) * QKPAD + r] = v.z * 0.125f;
        Qst[(c + 3) * QKPAD + r] = v.w * 0.125f;
    }

    float m[4], l[4], o[4][4];
    #pragma unroll
    for (int i = 0; i < 4; i++) {
        m[i] = -1e30f; l[i] = 0.f;
        #pragma unroll
        for (int j = 0; j < 4; j++) o[i][j] = 0.f;
    }

    const int NT = (Nc + 63) / 64;
    for (int kt = 0; kt < NT; kt++) {
        const int k0 = kt * 64;
        __syncthreads();
        #pragma unroll
        for (int it = 0; it < 4; it++) {
            int i4 = tid + it * 256;
            int r = i4 >> 4;
            int c = (i4 & 15) * 4;
            int kr = k0 + r;
            float4 kv = make_float4(0.f, 0.f, 0.f, 0.f);
            float4 vv = make_float4(0.f, 0.f, 0.f, 0.f);
            if (kr < Nc) {
                kv = *(const float4*)(Kp + (size_t)kr * HDc + c);
                vv = *(const float4*)(Vp + (size_t)kr * HDc + c);
            }
            Kst[(c + 0) * QKPAD + r] = kv.x;
            Kst[(c + 1) * QKPAD + r] = kv.y;
            Kst[(c + 2) * QKPAD + r] = kv.z;
            Kst[(c + 3) * QKPAD + r] = kv.w;
            *(float4*)(Vs + r * 64 + c) = vv;
        }
        __syncthreads();

        float s[4][4];
        #pragma unroll
        for (int i = 0; i < 4; i++)
            #pragma unroll
            for (int j = 0; j < 4; j++) s[i][j] = 0.f;
        #pragma unroll 8
        for (int d = 0; d < HDc; d++) {
            float4 a = *(const float4*)(Qst + d * QKPAD + trow);
            float4 b = *(const float4*)(Kst + d * QKPAD + tcol);
            float av[4] = {a.x, a.y, a.z, a.w};
            float bv[4] = {b.x, b.y, b.z, b.w};
            #pragma unroll
            for (int i = 0; i < 4; i++)
                #pragma unroll
                for (int j = 0; j < 4; j++) s[i][j] += av[i] * bv[j];
        }
        #pragma unroll
        for (int j = 0; j < 4; j++)
            if (k0 + tcol + j >= Nc) {
                #pragma unroll
                for (int i = 0; i < 4; i++) s[i][j] = -1e30f;
            }
        #pragma unroll
        for (int i = 0; i < 4; i++) {
            float mx = fmaxf(fmaxf(s[i][0], s[i][1]), fmaxf(s[i][2], s[i][3]));
            #pragma unroll
            for (int off = 8; off; off >>= 1)
                mx = fmaxf(mx, __shfl_xor_sync(0xffffffffu, mx, off, 16));
            float mn = fmaxf(m[i], mx);
            float corr = __expf(m[i] - mn);
            float rsum = 0.f;
            #pragma unroll
            for (int j = 0; j < 4; j++) {
                float p = __expf(s[i][j] - mn);
                s[i][j] = p; rsum += p;
            }
            #pragma unroll
            for (int off = 8; off; off >>= 1)
                rsum += __shfl_xor_sync(0xffffffffu, rsum, off, 16);
            l[i] = l[i] * corr + rsum;
            m[i] = mn;
            #pragma unroll
            for (int j = 0; j < 4; j++) o[i][j] *= corr;
        }
        #pragma unroll
        for (int i = 0; i < 4; i++)
            *(float4*)(Ps + (trow + i) * 64 + tcol) = *(float4*)&s[i][0];
        __syncthreads();
        for (int k = 0; k < 64; k += 4) {
            float pr[4][4];
            #pragma unroll
            for (int i = 0; i < 4; i++)
                *(float4*)&pr[i][0] = *(const float4*)(Ps + (trow + i) * 64 + k);
            #pragma unroll
            for (int kk = 0; kk < 4; kk++) {
                float4 bv = *(const float4*)(Vs + (k + kk) * 64 + tcol);
                #pragma unroll
                for (int i = 0; i < 4; i++) {
                    o[i][0] += pr[i][kk] * bv.x;
                    o[i][1] += pr[i][kk] * bv.y;
                    o[i][2] += pr[i][kk] * bv.z;
                    o[i][3] += pr[i][kk] * bv.w;
                }
            }
        }
    }
    #pragma unroll
    for (int i = 0; i < 4; i++) {
        int qr = q0 + trow + i;
        if (qr < Nc) {
            float inv = 1.f / l[i];
            float4 r4 = make_float4(o[i][0] * inv, o[i][1] * inv,
                                    o[i][2] * inv, o[i][3] * inv);
            *(float4*)(g_o + (size_t)bh * Nc * HDc + (size_t)qr * HDc + tcol) = r4;
        }
    }
}

// ---------------- launch ------------------------------------------------------
extern "C" void kernel_launch(void* const* d_in, const int* in_sizes, int n_in,
                              void* d_out, int out_size)
{
    const float* x  = (const float*)d_in[0];
    const float* lg = (const float*)d_in[1];
    const float* lb = (const float*)d_in[2];
    const float* wq = (const float*)d_in[3];
    const float* wp = (const float*)d_in[4];
    const float* bp = (const float*)d_in[5];
    float* out = (float*)d_out;
    (void)in_sizes; (void)n_in; (void)out_size;

    cudaFuncSetAttribute(attn_k, cudaFuncAttributeMaxDynamicSharedMemorySize,
                         ATTN_SMEM);
    cudaFuncSetAttribute(mma_gemm_k<0>, cudaFuncAttributeMaxDynamicSharedMemorySize,
                         GEMM_SMEM);
    cudaFuncSetAttribute(mma_gemm_k<1>, cudaFuncAttributeMaxDynamicSharedMemorySize,
                         GEMM_SMEM);

    ln_stats_k<<<Mc, 256>>>(x);
    split_ln_k<<<MP, 256>>>(x, lg, lb);
    split_w_k<0><<<(E3c * Dc + 255) / 256, 256>>>(wq, E3c * Dc);
    split_w_k<1><<<(Dc * Dc + 255) / 256, 256>>>(wp, Dc * Dc);
    mma_gemm_k<0><<<dim3(E3c / BN, MP / BM), 256, GEMM_SMEM>>>(nullptr, nullptr);
    rope_k<<<(Bc * Nc * Hc * 32 + 255) / 256, 256>>>();
    attn_k<<<dim3(Bc * Hc, (Nc + 63) / 64), 256, ATTN_SMEM>>>();
    split_o_k<<<MP, 256>>>();
    mma_gemm_k<1><<<dim3(Dc / BN, MP / BM), 256, GEMM_SMEM>>>(bp, out);
}

// round 11
// speedup vs baseline: 2.6979x; 1.8927x over previous
#include <cuda_runtime.h>
#include <cuda_bf16.h>
#include <cstdint>
#include <math.h>

#define Bc   8
#define Nc   1025
#define Dc   768
#define Hc   12
#define HDc  64
#define E3c  2304
#define Mc   (Bc*Nc)      // 8200
#define MP   8320         // M padded to 65*128

// ---- mma.sync gemm config ----
#define BM 128
#define BN 128
#define BK 32
#define NK (Dc/BK)              // 24
#define ROWB 80
#define ARR_BYTES (128*ROWB)
#define STAGE_BYTES (4*ARR_BYTES)
#define GEMM_SMEM (2*STAGE_BYTES) // 81920

// ---- attention config ----
#define AQ 128
#define PADR 128
#define KVARR 8192              // 64 rows * 128B
#define KVSTAGE (4*KVARR)       // Kh,Kl,Vh,Vl
#define QARR 16384              // 128 rows * 128B
#define ATTN_SMEM (2*KVSTAGE + 2*QARR)  // 98304

// ---------------- scratch ----------------
__device__ float g_mu [Mc];
__device__ float g_rs [Mc];
__device__ float g_qkv[(size_t)Mc * E3c];
__device__ __nv_bfloat16 g_ahi[(size_t)MP * Dc];
__device__ __nv_bfloat16 g_alo[(size_t)MP * Dc];
__device__ __nv_bfloat16 g_ohi[(size_t)MP * Dc];
__device__ __nv_bfloat16 g_olo[(size_t)MP * Dc];
__device__ __nv_bfloat16 g_wqhi[(size_t)E3c * Dc];
__device__ __nv_bfloat16 g_wqlo[(size_t)E3c * Dc];
__device__ __nv_bfloat16 g_wphi[(size_t)Dc * Dc];
__device__ __nv_bfloat16 g_wplo[(size_t)Dc * Dc];
// attention operands, bf16 hi/lo, [B,H,N,64] (+pad rows)
#define QKV_ROWS ((size_t)Bc*Hc*Nc + PADR)
__device__ __nv_bfloat16 g_qh[QKV_ROWS * HDc];
__device__ __nv_bfloat16 g_ql[QKV_ROWS * HDc];
__device__ __nv_bfloat16 g_kh[QKV_ROWS * HDc];
__device__ __nv_bfloat16 g_kl[QKV_ROWS * HDc];
__device__ __nv_bfloat16 g_vh[QKV_ROWS * HDc];
__device__ __nv_bfloat16 g_vl[QKV_ROWS * HDc];

// ================= helpers =================
__device__ __forceinline__ uint32_t smem_u32(const void* p) {
    uint32_t a;
    asm("{ .reg .u64 t; cvta.to.shared.u64 t, %1; cvt.u32.u64 %0, t; }"
        : "=r"(a) : "l"(p));
    return a;
}

#define LDM4(r0, r1, r2, r3, addr) \
    asm volatile("ldmatrix.sync.aligned.m8n8.x4.shared.b16 {%0,%1,%2,%3}, [%4];" \
        : "=r"(r0), "=r"(r1), "=r"(r2), "=r"(r3) : "r"(addr))

#define LDM4T(r0, r1, r2, r3, addr) \
    asm volatile("ldmatrix.sync.aligned.m8n8.x4.trans.shared.b16 {%0,%1,%2,%3}, [%4];" \
        : "=r"(r0), "=r"(r1), "=r"(r2), "=r"(r3) : "r"(addr))

#define MMA16816(d, a, b0, b1) \
    asm volatile("mma.sync.aligned.m16n8k16.row.col.f32.bf16.bf16.f32 " \
        "{%0,%1,%2,%3}, {%4,%5,%6,%7}, {%8,%9}, {%0,%1,%2,%3};" \
        : "+f"((d)[0]), "+f"((d)[1]), "+f"((d)[2]), "+f"((d)[3]) \
        : "r"((a)[0]), "r"((a)[1]), "r"((a)[2]), "r"((a)[3]), "r"(b0), "r"(b1))

__device__ __forceinline__ void cp16(uint32_t dst, const void* src) {
    asm volatile("cp.async.cg.shared.global [%0], [%1], 16;" :: "r"(dst), "l"(src));
}
__device__ __forceinline__ void cp_commit() {
    asm volatile("cp.async.commit_group;" ::: "memory");
}
template<int N>
__device__ __forceinline__ void cp_wait() {
    asm volatile("cp.async.wait_group %0;" :: "n"(N) : "memory");
}

// pack two fp32 -> bf16x2 {lo=x, hi=y}
__device__ __forceinline__ uint32_t pack_bf2(float x, float y) {
    uint32_t r;
    asm("cvt.rn.bf16x2.f32 %0, %1, %2;" : "=r"(r) : "f"(y), "f"(x));
    return r;
}
// hi/lo split of a pair; returns hi-pack, lo-pack
__device__ __forceinline__ void split_pair(float x, float y, uint32_t& hp, uint32_t& lp) {
    hp = pack_bf2(x, y);
    float h0 = __uint_as_float(hp << 16);
    float h1 = __uint_as_float(hp & 0xffff0000u);
    lp = pack_bf2(x - h0, y - h1);
}

__device__ __forceinline__ uint32_t swz(uint32_t base, int row, int chunk) {
    return base + row * 128 + ((chunk ^ (row & 7)) << 4);
}

// ---------------- 1) LayerNorm row stats ------------------------------------
__global__ __launch_bounds__(256) void ln_stats_k(const float* __restrict__ x)
{
    const int row = blockIdx.x;
    const float* xr = x + (size_t)row * Dc;
    float s = 0.f, s2 = 0.f;
    for (int i = threadIdx.x; i < Dc; i += 256) {
        float v = xr[i];
        s += v; s2 += v * v;
    }
    #pragma unroll
    for (int o = 16; o; o >>= 1) {
        s  += __shfl_xor_sync(0xffffffffu, s,  o);
        s2 += __shfl_xor_sync(0xffffffffu, s2, o);
    }
    __shared__ float sh[16];
    const int w = threadIdx.x >> 5;
    if ((threadIdx.x & 31) == 0) { sh[w] = s; sh[8 + w] = s2; }
    __syncthreads();
    if (threadIdx.x < 32) {
        s  = (threadIdx.x < 8) ? sh[threadIdx.x]     : 0.f;
        s2 = (threadIdx.x < 8) ? sh[8 + threadIdx.x] : 0.f;
        #pragma unroll
        for (int o = 4; o; o >>= 1) {
            s  += __shfl_xor_sync(0xffffffffu, s,  o);
            s2 += __shfl_xor_sync(0xffffffffu, s2, o);
        }
        if (threadIdx.x == 0) {
            float mu  = s  * (1.f / Dc);
            float var = s2 * (1.f / Dc) - mu * mu;
            g_mu[row] = mu;
            g_rs[row] = rsqrtf(var + 1e-5f);
        }
    }
}

// ---------------- splits ------------------------------------------------------
__device__ __forceinline__ void split_bf16(float v, __nv_bfloat16& h, __nv_bfloat16& l) {
    h = __float2bfloat16(v);
    l = __float2bfloat16(v - __bfloat162float(h));
}

__global__ __launch_bounds__(256) void split_ln_k(
    const float* __restrict__ x, const float* __restrict__ lg, const float* __restrict__ lb)
{
    const int m = blockIdx.x;
    const bool ok = m < Mc;
    const float mu = ok ? g_mu[m] : 0.f;
    const float rs = ok ? g_rs[m] : 0.f;
    for (int c = threadIdx.x; c < Dc; c += 256) {
        float v = 0.f;
        if (ok) v = (x[(size_t)m * Dc + c] - mu) * rs * lg[c] + lb[c];
        __nv_bfloat16 h, l;
        split_bf16(v, h, l);
        g_ahi[(size_t)m * Dc + c] = h;
        g_alo[(size_t)m * Dc + c] = l;
    }
}

template<int WHICH>
__global__ void split_w_k(const float* __restrict__ w, int n)
{
    int i = blockIdx.x * 256 + threadIdx.x;
    if (i >= n) return;
    __nv_bfloat16 h, l;
    split_bf16(w[i], h, l);
    if (WHICH == 0) { g_wqhi[i] = h; g_wqlo[i] = l; }
    else            { g_wphi[i] = h; g_wplo[i] = l; }
}

__global__ void zero_pad_k()
{
    int i = blockIdx.x * 256 + threadIdx.x;
    if (i >= PADR * HDc) return;
    size_t off = (size_t)Bc * Hc * Nc * HDc + i;
    __nv_bfloat16 z = __float2bfloat16(0.f);
    g_qh[off] = z; g_ql[off] = z;
    g_kh[off] = z; g_kl[off] = z;
    g_vh[off] = z; g_vl[off] = z;
}

// ---------------- 2) mma.sync 3xBF16 GEMM ------------------------------------
template<int MODE>
__global__ __launch_bounds__(256, 1) void mma_gemm_k(
    const float* __restrict__ bias, float* __restrict__ outp)
{
    constexpr int E = (MODE == 0) ? E3c : Dc;
    const __nv_bfloat16* __restrict__ Ahi = (MODE == 0) ? g_ahi : g_ohi;
    const __nv_bfloat16* __restrict__ Alo = (MODE == 0) ? g_alo : g_olo;
    const __nv_bfloat16* __restrict__ Bhi = (MODE == 0) ? g_wqhi : g_wphi;
    const __nv_bfloat16* __restrict__ Blo = (MODE == 0) ? g_wqlo : g_wplo;
    float* __restrict__ C = (MODE == 0) ? g_qkv : outp;

    extern __shared__ char smem[];
    const uint32_t sb = smem_u32(smem);
    const int tid  = threadIdx.x;
    const int wid  = tid >> 5;
    const int lane = tid & 31;
    const int wm = wid >> 2;
    const int wn = wid & 3;
    const int e0 = blockIdx.x * BN;
    const int m0 = blockIdx.y * BM;

    const __nv_bfloat16* gA[4] = {
        Ahi + (size_t)m0 * Dc, Alo + (size_t)m0 * Dc,
        Bhi + (size_t)e0 * Dc, Blo + (size_t)e0 * Dc };

    auto load_stage = [&](int s, int k0) {
        const uint32_t stg = sb + s * STAGE_BYTES;
        #pragma unroll
        for (int arr = 0; arr < 4; arr++) {
            #pragma unroll
            for (int i = 0; i < 2; i++) {
                int ci = tid + i * 256;
                int r = ci >> 2, c = ci & 3;
                cp16(stg + arr * ARR_BYTES + r * ROWB + c * 16,
                     gA[arr] + (size_t)r * Dc + k0 + c * 8);
            }
        }
        cp_commit();
    };

    float acc[4][4][4];
    #pragma unroll
    for (int i = 0; i < 4; i++)
        #pragma unroll
        for (int j = 0; j < 4; j++)
            #pragma unroll
            for (int q = 0; q < 4; q++) acc[i][j][q] = 0.f;

    const int a_row   = (lane & 7) + ((lane >> 3) & 1) * 8;
    const int a_chunk = (lane >> 4) & 1;
    const int b_row   = (lane & 7) + ((lane >> 4) & 1) * 8;
    const int b_chunk = (lane >> 3) & 1;

    load_stage(0, 0);

    for (int it = 0; it < NK; it++) {
        if (it + 1 < NK) load_stage((it + 1) & 1, (it + 1) * BK);
        if (it + 1 < NK) cp_wait<1>(); else cp_wait<0>();
        __syncthreads();

        const uint32_t stg = sb + (it & 1) * STAGE_BYTES;
        const uint32_t aHi = stg;
        const uint32_t aLo = stg + ARR_BYTES;
        const uint32_t bHi = stg + 2 * ARR_BYTES;
        const uint32_t bLo = stg + 3 * ARR_BYTES;

        #pragma unroll
        for (int k16 = 0; k16 < 2; k16++) {
            uint32_t ah[4][4], al[4][4], bh[2][4], bl[2][4];
            #pragma unroll
            for (int i = 0; i < 4; i++) {
                uint32_t ro = (uint32_t)((wm * 64 + i * 16 + a_row) * ROWB
                                         + (k16 * 2 + a_chunk) * 16);
                LDM4(ah[i][0], ah[i][1], ah[i][2], ah[i][3], aHi + ro);
                LDM4(al[i][0], al[i][1], al[i][2], al[i][3], aLo + ro);
            }
            #pragma unroll
            for (int j2 = 0; j2 < 2; j2++) {
                uint32_t ro = (uint32_t)((wn * 32 + j2 * 16 + b_row) * ROWB
                                         + (k16 * 2 + b_chunk) * 16);
                LDM4(bh[j2][0], bh[j2][1], bh[j2][2], bh[j2][3], bHi + ro);
                LDM4(bl[j2][0], bl[j2][1], bl[j2][2], bl[j2][3], bLo + ro);
            }
            #pragma unroll
            for (int i = 0; i < 4; i++) {
                #pragma unroll
                for (int j = 0; j < 4; j++) {
                    uint32_t h0 = bh[j >> 1][(j & 1) * 2];
                    uint32_t h1 = bh[j >> 1][(j & 1) * 2 + 1];
                    uint32_t l0 = bl[j >> 1][(j & 1) * 2];
                    uint32_t l1 = bl[j >> 1][(j & 1) * 2 + 1];
                    MMA16816(acc[i][j], ah[i], h0, h1);
                    MMA16816(acc[i][j], ah[i], l0, l1);
                    MMA16816(acc[i][j], al[i], h0, h1);
                }
            }
        }
        __syncthreads();
    }

    const int gid = lane >> 2, tig = lane & 3;
    #pragma unroll
    for (int i = 0; i < 4; i++) {
        #pragma unroll
        for (int j = 0; j < 4; j++) {
            int col  = e0 + wn * 32 + j * 8 + tig * 2;
            int row0 = m0 + wm * 64 + i * 16 + gid;
            int row1 = row0 + 8;
            float2 v0 = make_float2(acc[i][j][0], acc[i][j][1]);
            float2 v1 = make_float2(acc[i][j][2], acc[i][j][3]);
            if (MODE == 1) {
                float2 bz = *(const float2*)(bias + col);
                v0.x += bz.x; v0.y += bz.y;
                v1.x += bz.x; v1.y += bz.y;
            }
            if (row0 < Mc) *(float2*)(C + (size_t)row0 * E + col) = v0;
            if (row1 < Mc) *(float2*)(C + (size_t)row1 * E + col) = v1;
        }
    }
}

// ---------------- 3) RoPE -> bf16 hi/lo [B,H,N,64] ---------------------------
__global__ void rope_k()
{
    const int TOT = Bc * Nc * Hc * 32;
    int idx = blockIdx.x * 256 + threadIdx.x;
    if (idx >= TOT) return;
    int j = idx & 31;
    int h = (idx >> 5) % Hc;
    int t = idx / (32 * Hc);
    int b = t / Nc;
    int n = t - b * Nc;
    int f = j & 15;
    int pos = 0;
    if (n != 0) {
        int p = n - 1;
        pos = (j < 16) ? (p >> 5) : (p & 31);
    }
    int d0 = (j < 16) ? (2 * f) : (32 + 2 * f);
    float inv = expf(-(float)f * 0.5756462732485114f);
    float ang = (float)pos * inv;
    float sn, cs;
    sincosf(ang, &sn, &cs);
    size_t src = (size_t)t * E3c + h * HDc + d0;
    float2 q2 = *(const float2*)(g_qkv + src);
    float2 k2 = *(const float2*)(g_qkv + src + Dc);
    float2 v2 = *(const float2*)(g_qkv + src + 2 * Dc);
    float qx = (q2.x * cs - q2.y * sn) * 0.125f;
    float qy = (q2.y * cs + q2.x * sn) * 0.125f;
    float kx = k2.x * cs - k2.y * sn;
    float ky = k2.y * cs + k2.x * sn;
    size_t dst = (((size_t)(b * Hc + h)) * Nc + n) * HDc + d0;
    uint32_t hp, lp;
    split_pair(qx, qy, hp, lp);
    *(uint32_t*)(g_qh + dst) = hp;  *(uint32_t*)(g_ql + dst) = lp;
    split_pair(kx, ky, hp, lp);
    *(uint32_t*)(g_kh + dst) = hp;  *(uint32_t*)(g_kl + dst) = lp;
    split_pair(v2.x, v2.y, hp, lp);
    *(uint32_t*)(g_vh + dst) = hp;  *(uint32_t*)(g_vl + dst) = lp;
}

// ---------------- 4) Flash attention, mma.sync 3xBF16 ------------------------
__global__ __launch_bounds__(256, 1) void attn2_k()
{
    extern __shared__ char sm[];
    const uint32_t sb = smem_u32(sm);
    const int tid = threadIdx.x, wid = tid >> 5, lane = tid & 31;
    const int bh = blockIdx.x, q0 = blockIdx.y * AQ;
    const int bI = bh / Hc, hI = bh % Hc;
    const size_t hb = (size_t)bh * Nc * HDc;
    const uint32_t Qh = sb + 2 * KVSTAGE, Ql = Qh + QARR;

    // Q tile -> smem (group 0)
    {
        const __nv_bfloat16* qhp = g_qh + hb + (size_t)q0 * HDc;
        const __nv_bfloat16* qlp = g_ql + hb + (size_t)q0 * HDc;
        #pragma unroll
        for (int t = 0; t < 4; t++) {
            int idx = tid + t * 256;
            int r = idx >> 3, c = idx & 7;
            cp16(swz(Qh, r, c), qhp + (size_t)r * HDc + c * 8);
            cp16(swz(Ql, r, c), qlp + (size_t)r * HDc + c * 8);
        }
        cp_commit();
    }
    auto load_kv = [&](int s, int kt) {
        uint32_t st = sb + s * KVSTAGE;
        const size_t kb = hb + (size_t)kt * 64 * HDc;
        #pragma unroll
        for (int t = 0; t < 2; t++) {
            int idx = tid + t * 256;
            int r = idx >> 3, c = idx & 7;
            size_t go = kb + (size_t)r * HDc + c * 8;
            cp16(swz(st,             r, c), g_kh + go);
            cp16(swz(st +     KVARR, r, c), g_kl + go);
            cp16(swz(st + 2 * KVARR, r, c), g_vh + go);
            cp16(swz(st + 3 * KVARR, r, c), g_vl + go);
        }
        cp_commit();
    };
    load_kv(0, 0);

    cp_wait<1>();      // Q group done
    __syncthreads();
    uint32_t qh[4][4], ql[4][4];
    #pragma unroll
    for (int c = 0; c < 4; c++) {
        int row = wid * 16 + (lane & 15);
        int ch  = c * 2 + (lane >> 4);
        LDM4(qh[c][0], qh[c][1], qh[c][2], qh[c][3], swz(Qh, row, ch));
        LDM4(ql[c][0], ql[c][1], ql[c][2], ql[c][3], swz(Ql, row, ch));
    }

    float out[8][4];
    #pragma unroll
    for (int i = 0; i < 8; i++)
        #pragma unroll
        for (int q = 0; q < 4; q++) out[i][q] = 0.f;
    float m0 = -1e30f, m1 = -1e30f, l0 = 0.f, l1 = 0.f;

    const int NT = (Nc + 63) / 64;   // 17
    for (int kt = 0; kt < NT; kt++) {
        if (kt + 1 < NT) load_kv((kt + 1) & 1, kt + 1);
        if (kt + 1 < NT) cp_wait<1>(); else cp_wait<0>();
        __syncthreads();
        const uint32_t st = sb + (kt & 1) * KVSTAGE;
        const uint32_t Kh = st, Kl = st + KVARR, Vh = st + 2 * KVARR, Vl = st + 3 * KVARR;

        // ---- S = Q K^T ----
        float sac[8][4];
        #pragma unroll
        for (int i = 0; i < 8; i++)
            #pragma unroll
            for (int q = 0; q < 4; q++) sac[i][q] = 0.f;
        #pragma unroll
        for (int c = 0; c < 4; c++) {
            #pragma unroll
            for (int g = 0; g < 4; g++) {
                int row = g * 16 + (lane & 15);
                int ch  = c * 2 + (lane >> 4);
                uint32_t kh0, kh1, kh2, kh3, kl0, kl1, kl2, kl3;
                LDM4(kh0, kh1, kh2, kh3, swz(Kh, row, ch));
                LDM4(kl0, kl1, kl2, kl3, swz(Kl, row, ch));
                MMA16816(sac[2 * g],     qh[c], kh0, kh2);
                MMA16816(sac[2 * g],     qh[c], kl0, kl2);
                MMA16816(sac[2 * g],     ql[c], kh0, kh2);
                MMA16816(sac[2 * g + 1], qh[c], kh1, kh3);
                MMA16816(sac[2 * g + 1], qh[c], kl1, kl3);
                MMA16816(sac[2 * g + 1], ql[c], kh1, kh3);
            }
        }
        // ---- mask ----
        const int k0 = kt * 64;
        #pragma unroll
        for (int j = 0; j < 8; j++) {
            int kc = k0 + j * 8 + 2 * (lane & 3);
            if (kc     >= Nc) { sac[j][0] = -1e30f; sac[j][2] = -1e30f; }
            if (kc + 1 >= Nc) { sac[j][1] = -1e30f; sac[j][3] = -1e30f; }
        }
        // ---- online softmax ----
        float mx0 = -1e30f, mx1 = -1e30f;
        #pragma unroll
        for (int j = 0; j < 8; j++) {
            mx0 = fmaxf(mx0, fmaxf(sac[j][0], sac[j][1]));
            mx1 = fmaxf(mx1, fmaxf(sac[j][2], sac[j][3]));
        }
        mx0 = fmaxf(mx0, __shfl_xor_sync(0xffffffffu, mx0, 1));
        mx0 = fmaxf(mx0, __shfl_xor_sync(0xffffffffu, mx0, 2));
        mx1 = fmaxf(mx1, __shfl_xor_sync(0xffffffffu, mx1, 1));
        mx1 = fmaxf(mx1, __shfl_xor_sync(0xffffffffu, mx1, 2));
        float mn0 = fmaxf(m0, mx0), mn1 = fmaxf(m1, mx1);
        float co0 = __expf(m0 - mn0), co1 = __expf(m1 - mn1);
        m0 = mn0; m1 = mn1;
        float rs0 = 0.f, rs1 = 0.f;
        #pragma unroll
        for (int j = 0; j < 8; j++) {
            sac[j][0] = __expf(sac[j][0] - mn0);
            sac[j][1] = __expf(sac[j][1] - mn0);
            sac[j][2] = __expf(sac[j][2] - mn1);
            sac[j][3] = __expf(sac[j][3] - mn1);
            rs0 += sac[j][0] + sac[j][1];
            rs1 += sac[j][2] + sac[j][3];
        }
        rs0 += __shfl_xor_sync(0xffffffffu, rs0, 1);
        rs0 += __shfl_xor_sync(0xffffffffu, rs0, 2);
        rs1 += __shfl_xor_sync(0xffffffffu, rs1, 1);
        rs1 += __shfl_xor_sync(0xffffffffu, rs1, 2);
        l0 = l0 * co0 + rs0;
        l1 = l1 * co1 + rs1;
        #pragma unroll
        for (int jd = 0; jd < 8; jd++) {
            out[jd][0] *= co0; out[jd][1] *= co0;
            out[jd][2] *= co1; out[jd][3] *= co1;
        }
        // ---- O += P V ----
        #pragma unroll
        for (int kc2 = 0; kc2 < 4; kc2++) {
            uint32_t AH[4], AL[4];
            split_pair(sac[2 * kc2][0],     sac[2 * kc2][1],     AH[0], AL[0]);
            split_pair(sac[2 * kc2][2],     sac[2 * kc2][3],     AH[1], AL[1]);
            split_pair(sac[2 * kc2 + 1][0], sac[2 * kc2 + 1][1], AH[2], AL[2]);
            split_pair(sac[2 * kc2 + 1][2], sac[2 * kc2 + 1][3], AH[3], AL[3]);
            #pragma unroll
            for (int jd = 0; jd < 4; jd++) {
                int row = kc2 * 16 + (lane & 15);
                int ch  = jd * 2 + (lane >> 4);
                uint32_t v0, v1, v2, v3, w0, w1, w2, w3;
                LDM4T(v0, v1, v2, v3, swz(Vh, row, ch));
                LDM4T(w0, w1, w2, w3, swz(Vl, row, ch));
                MMA16816(out[2 * jd],     AH, v0, v1);
                MMA16816(out[2 * jd],     AH, w0, w1);
                MMA16816(out[2 * jd],     AL, v0, v1);
                MMA16816(out[2 * jd + 1], AH, v2, v3);
                MMA16816(out[2 * jd + 1], AH, w2, w3);
                MMA16816(out[2 * jd + 1], AL, v2, v3);
            }
        }
        __syncthreads();
    }
    // ---- epilogue: normalize, split, store bf16 hi/lo to [m][h*64+d] ----
    const float inv0 = 1.f / l0, inv1 = 1.f / l1;
    const int r = q0 + wid * 16 + (lane >> 2);
    #pragma unroll
    for (int jd = 0; jd < 8; jd++) {
        int col = hI * 64 + jd * 8 + 2 * (lane & 3);
        if (r < Nc) {
            size_t mi = ((size_t)(bI * Nc + r)) * Dc + col;
            uint32_t hp, lp;
            split_pair(out[jd][0] * inv0, out[jd][1] * inv0, hp, lp);
            *(uint32_t*)(g_ohi + mi) = hp;
            *(uint32_t*)(g_olo + mi) = lp;
        }
        if (r + 8 < Nc) {
            size_t mi = ((size_t)(bI * Nc + r + 8)) * Dc + col;
            uint32_t hp, lp;
            split_pair(out[jd][2] * inv1, out[jd][3] * inv1, hp, lp);
            *(uint32_t*)(g_ohi + mi) = hp;
            *(uint32_t*)(g_olo + mi) = lp;
        }
    }
}

// ---------------- launch ------------------------------------------------------
extern "C" void kernel_launch(void* const* d_in, const int* in_sizes, int n_in,
                              void* d_out, int out_size)
{
    const float* x  = (const float*)d_in[0];
    const float* lg = (const float*)d_in[1];
    const float* lb = (const float*)d_in[2];
    const float* wq = (const float*)d_in[3];
    const float* wp = (const float*)d_in[4];
    const float* bp = (const float*)d_in[5];
    float* out = (float*)d_out;
    (void)in_sizes; (void)n_in; (void)out_size;

    cudaFuncSetAttribute(mma_gemm_k<0>, cudaFuncAttributeMaxDynamicSharedMemorySize, GEMM_SMEM);
    cudaFuncSetAttribute(mma_gemm_k<1>, cudaFuncAttributeMaxDynamicSharedMemorySize, GEMM_SMEM);
    cudaFuncSetAttribute(attn2_k, cudaFuncAttributeMaxDynamicSharedMemorySize, ATTN_SMEM);

    ln_stats_k<<<Mc, 256>>>(x);
    split_ln_k<<<MP, 256>>>(x, lg, lb);
    split_w_k<0><<<(E3c * Dc + 255) / 256, 256>>>(wq, E3c * Dc);
    split_w_k<1><<<(Dc * Dc + 255) / 256, 256>>>(wp, Dc * Dc);
    zero_pad_k<<<(PADR * HDc + 255) / 256, 256>>>();
    mma_gemm_k<0><<<dim3(E3c / BN, MP / BM), 256, GEMM_SMEM>>>(nullptr, nullptr);
    rope_k<<<(Bc * Nc * Hc * 32 + 255) / 256, 256>>>();
    attn2_k<<<dim3(Bc * Hc, (Nc + AQ - 1) / AQ), 256, ATTN_SMEM>>>();
    mma_gemm_k<1><<<dim3(Dc / BN, MP / BM), 256, GEMM_SMEM>>>(bp, out);
}

// round 12
// speedup vs baseline: 2.9976x; 1.1111x over previous
#include <cuda_runtime.h>
#include <cuda_bf16.h>
#include <cstdint>
#include <math.h>

#define Bc   8
#define Nc   1025
#define Dc   768
#define Hc   12
#define HDc  64
#define E3c  2304
#define Mc   (Bc*Nc)      // 8200
#define MP   8320         // M padded to 65*128

// ---- mma.sync gemm config ----
#define BM 128
#define BN 128
#define BK 32
#define NK (Dc/BK)              // 24
#define ROWB 80
#define ARR_BYTES (128*ROWB)
#define STAGE_BYTES (4*ARR_BYTES)
#define GEMM_SMEM (2*STAGE_BYTES) // 81920

// ---- attention config ----
#define AQ 128
#define PADR 128
#define KVARR 8192              // 64 rows * 128B
#define KVSTAGE (4*KVARR)       // Kh,Kl,Vh,Vl
#define QARR 16384              // 128 rows * 128B
#define ATTN_SMEM (2*KVSTAGE + 2*QARR)  // 98304

// ---------------- scratch ----------------
__device__ __nv_bfloat16 g_ahi[(size_t)MP * Dc];
__device__ __nv_bfloat16 g_alo[(size_t)MP * Dc];
__device__ __nv_bfloat16 g_ohi[(size_t)MP * Dc];
__device__ __nv_bfloat16 g_olo[(size_t)MP * Dc];
__device__ __nv_bfloat16 g_wqhi[(size_t)E3c * Dc];
__device__ __nv_bfloat16 g_wqlo[(size_t)E3c * Dc];
__device__ __nv_bfloat16 g_wphi[(size_t)Dc * Dc];
__device__ __nv_bfloat16 g_wplo[(size_t)Dc * Dc];
// attention operands, bf16 hi/lo, [B,H,N,64] (+pad rows)
#define QKV_ROWS ((size_t)Bc*Hc*Nc + PADR)
__device__ __nv_bfloat16 g_qh[QKV_ROWS * HDc];
__device__ __nv_bfloat16 g_ql[QKV_ROWS * HDc];
__device__ __nv_bfloat16 g_kh[QKV_ROWS * HDc];
__device__ __nv_bfloat16 g_kl[QKV_ROWS * HDc];
__device__ __nv_bfloat16 g_vh[QKV_ROWS * HDc];
__device__ __nv_bfloat16 g_vl[QKV_ROWS * HDc];

// ================= helpers =================
__device__ __forceinline__ uint32_t smem_u32(const void* p) {
    uint32_t a;
    asm("{ .reg .u64 t; cvta.to.shared.u64 t, %1; cvt.u32.u64 %0, t; }"
        : "=r"(a) : "l"(p));
    return a;
}

#define LDM4(r0, r1, r2, r3, addr) \
    asm volatile("ldmatrix.sync.aligned.m8n8.x4.shared.b16 {%0,%1,%2,%3}, [%4];" \
        : "=r"(r0), "=r"(r1), "=r"(r2), "=r"(r3) : "r"(addr))

#define LDM4T(r0, r1, r2, r3, addr) \
    asm volatile("ldmatrix.sync.aligned.m8n8.x4.trans.shared.b16 {%0,%1,%2,%3}, [%4];" \
        : "=r"(r0), "=r"(r1), "=r"(r2), "=r"(r3) : "r"(addr))

#define MMA16816(d, a, b0, b1) \
    asm volatile("mma.sync.aligned.m16n8k16.row.col.f32.bf16.bf16.f32 " \
        "{%0,%1,%2,%3}, {%4,%5,%6,%7}, {%8,%9}, {%0,%1,%2,%3};" \
        : "+f"((d)[0]), "+f"((d)[1]), "+f"((d)[2]), "+f"((d)[3]) \
        : "r"((a)[0]), "r"((a)[1]), "r"((a)[2]), "r"((a)[3]), "r"(b0), "r"(b1))

__device__ __forceinline__ void cp16(uint32_t dst, const void* src) {
    asm volatile("cp.async.cg.shared.global [%0], [%1], 16;" :: "r"(dst), "l"(src));
}
__device__ __forceinline__ void cp_commit() {
    asm volatile("cp.async.commit_group;" ::: "memory");
}
template<int N>
__device__ __forceinline__ void cp_wait() {
    asm volatile("cp.async.wait_group %0;" :: "n"(N) : "memory");
}

// pack two fp32 -> bf16x2 {lo=x, hi=y}
__device__ __forceinline__ uint32_t pack_bf2(float x, float y) {
    uint32_t r;
    asm("cvt.rn.bf16x2.f32 %0, %1, %2;" : "=r"(r) : "f"(y), "f"(x));
    return r;
}
// hi/lo split of a pair; returns hi-pack, lo-pack
__device__ __forceinline__ void split_pair(float x, float y, uint32_t& hp, uint32_t& lp) {
    hp = pack_bf2(x, y);
    float h0 = __uint_as_float(hp << 16);
    float h1 = __uint_as_float(hp & 0xffff0000u);
    lp = pack_bf2(x - h0, y - h1);
}

__device__ __forceinline__ uint32_t swz(uint32_t base, int row, int chunk) {
    return base + row * 128 + ((chunk ^ (row & 7)) << 4);
}

// ---------------- 1) LayerNorm + bf16 hi/lo split (fused) --------------------
__global__ __launch_bounds__(256) void lnsplit_k(
    const float* __restrict__ x, const float* __restrict__ lg, const float* __restrict__ lb)
{
    const int row = blockIdx.x;
    const float* xr = x + (size_t)row * Dc;
    float v3[3];
    float s = 0.f, s2 = 0.f;
    #pragma unroll
    for (int t = 0; t < 3; t++) {
        float v = xr[threadIdx.x + t * 256];
        v3[t] = v;
        s += v; s2 += v * v;
    }
    #pragma unroll
    for (int o = 16; o; o >>= 1) {
        s  += __shfl_xor_sync(0xffffffffu, s,  o);
        s2 += __shfl_xor_sync(0xffffffffu, s2, o);
    }
    __shared__ float sh[16];
    __shared__ float smu, srs;
    const int w = threadIdx.x >> 5;
    if ((threadIdx.x & 31) == 0) { sh[w] = s; sh[8 + w] = s2; }
    __syncthreads();
    if (threadIdx.x < 32) {
        s  = (threadIdx.x < 8) ? sh[threadIdx.x]     : 0.f;
        s2 = (threadIdx.x < 8) ? sh[8 + threadIdx.x] : 0.f;
        #pragma unroll
        for (int o = 4; o; o >>= 1) {
            s  += __shfl_xor_sync(0xffffffffu, s,  o);
            s2 += __shfl_xor_sync(0xffffffffu, s2, o);
        }
        if (threadIdx.x == 0) {
            float mu  = s  * (1.f / Dc);
            float var = s2 * (1.f / Dc) - mu * mu;
            smu = mu;
            srs = rsqrtf(var + 1e-5f);
        }
    }
    __syncthreads();
    const float mu = smu, rs = srs;
    #pragma unroll
    for (int t = 0; t < 3; t++) {
        int c = threadIdx.x + t * 256;
        float v = (v3[t] - mu) * rs * lg[c] + lb[c];
        __nv_bfloat16 h = __float2bfloat16(v);
        __nv_bfloat16 l = __float2bfloat16(v - __bfloat162float(h));
        g_ahi[(size_t)row * Dc + c] = h;
        g_alo[(size_t)row * Dc + c] = l;
    }
}

template<int WHICH>
__global__ void split_w_k(const float* __restrict__ w, int n)
{
    int i = blockIdx.x * 256 + threadIdx.x;
    if (i >= n) return;
    float v = w[i];
    __nv_bfloat16 h = __float2bfloat16(v);
    __nv_bfloat16 l = __float2bfloat16(v - __bfloat162float(h));
    if (WHICH == 0) { g_wqhi[i] = h; g_wqlo[i] = l; }
    else            { g_wphi[i] = h; g_wplo[i] = l; }
}

__global__ void zero_pad_k()
{
    int i = blockIdx.x * 256 + threadIdx.x;
    if (i >= PADR * HDc) return;
    size_t off = (size_t)Bc * Hc * Nc * HDc + i;
    __nv_bfloat16 z = __float2bfloat16(0.f);
    g_qh[off] = z; g_ql[off] = z;
    g_kh[off] = z; g_kl[off] = z;
    g_vh[off] = z; g_vl[off] = z;
}

// ---------------- 2) mma.sync 3xBF16 GEMM ------------------------------------
// MODE 0: QKV gemm; epilogue applies RoPE + bf16 split -> g_q/k/v hi/lo
// MODE 1: out[m][e] = A(attn-out) @ w_proj^T + bias
template<int MODE>
__global__ __launch_bounds__(256, 2) void mma_gemm_k(
    const float* __restrict__ bias, float* __restrict__ outp)
{
    const __nv_bfloat16* __restrict__ Ahi = (MODE == 0) ? g_ahi : g_ohi;
    const __nv_bfloat16* __restrict__ Alo = (MODE == 0) ? g_alo : g_olo;
    const __nv_bfloat16* __restrict__ Bhi = (MODE == 0) ? g_wqhi : g_wphi;
    const __nv_bfloat16* __restrict__ Blo = (MODE == 0) ? g_wqlo : g_wplo;

    extern __shared__ char smem[];
    const uint32_t sb = smem_u32(smem);
    const int tid  = threadIdx.x;
    const int wid  = tid >> 5;
    const int lane = tid & 31;
    const int wm = wid >> 2;
    const int wn = wid & 3;
    const int e0 = blockIdx.x * BN;
    const int m0 = blockIdx.y * BM;

    const __nv_bfloat16* gA[4] = {
        Ahi + (size_t)m0 * Dc, Alo + (size_t)m0 * Dc,
        Bhi + (size_t)e0 * Dc, Blo + (size_t)e0 * Dc };

    auto load_stage = [&](int s, int k0) {
        const uint32_t stg = sb + s * STAGE_BYTES;
        #pragma unroll
        for (int arr = 0; arr < 4; arr++) {
            #pragma unroll
            for (int i = 0; i < 2; i++) {
                int ci = tid + i * 256;
                int r = ci >> 2, c = ci & 3;
                cp16(stg + arr * ARR_BYTES + r * ROWB + c * 16,
                     gA[arr] + (size_t)r * Dc + k0 + c * 8);
            }
        }
        cp_commit();
    };

    float acc[4][4][4];
    #pragma unroll
    for (int i = 0; i < 4; i++)
        #pragma unroll
        for (int j = 0; j < 4; j++)
            #pragma unroll
            for (int q = 0; q < 4; q++) acc[i][j][q] = 0.f;

    const int a_row   = (lane & 7) + ((lane >> 3) & 1) * 8;
    const int a_chunk = (lane >> 4) & 1;
    const int b_row   = (lane & 7) + ((lane >> 4) & 1) * 8;
    const int b_chunk = (lane >> 3) & 1;

    load_stage(0, 0);

    for (int it = 0; it < NK; it++) {
        if (it + 1 < NK) load_stage((it + 1) & 1, (it + 1) * BK);
        if (it + 1 < NK) cp_wait<1>(); else cp_wait<0>();
        __syncthreads();

        const uint32_t stg = sb + (it & 1) * STAGE_BYTES;
        const uint32_t aHi = stg;
        const uint32_t aLo = stg + ARR_BYTES;
        const uint32_t bHi = stg + 2 * ARR_BYTES;
        const uint32_t bLo = stg + 3 * ARR_BYTES;

        #pragma unroll
        for (int k16 = 0; k16 < 2; k16++) {
            uint32_t ah[4][4], al[4][4], bh[2][4], bl[2][4];
            #pragma unroll
            for (int i = 0; i < 4; i++) {
                uint32_t ro = (uint32_t)((wm * 64 + i * 16 + a_row) * ROWB
                                         + (k16 * 2 + a_chunk) * 16);
                LDM4(ah[i][0], ah[i][1], ah[i][2], ah[i][3], aHi + ro);
                LDM4(al[i][0], al[i][1], al[i][2], al[i][3], aLo + ro);
            }
            #pragma unroll
            for (int j2 = 0; j2 < 2; j2++) {
                uint32_t ro = (uint32_t)((wn * 32 + j2 * 16 + b_row) * ROWB
                                         + (k16 * 2 + b_chunk) * 16);
                LDM4(bh[j2][0], bh[j2][1], bh[j2][2], bh[j2][3], bHi + ro);
                LDM4(bl[j2][0], bl[j2][1], bl[j2][2], bl[j2][3], bLo + ro);
            }
            #pragma unroll
            for (int i = 0; i < 4; i++) {
                #pragma unroll
                for (int j = 0; j < 4; j++) {
                    uint32_t h0 = bh[j >> 1][(j & 1) * 2];
                    uint32_t h1 = bh[j >> 1][(j & 1) * 2 + 1];
                    uint32_t l0 = bl[j >> 1][(j & 1) * 2];
                    uint32_t l1 = bl[j >> 1][(j & 1) * 2 + 1];
                    MMA16816(acc[i][j], ah[i], h0, h1);
                    MMA16816(acc[i][j], ah[i], l0, l1);
                    MMA16816(acc[i][j], al[i], h0, h1);
                }
            }
        }
        __syncthreads();
    }

    // ---- epilogue ----
    const int gid = lane >> 2, tig = lane & 3;
    if (MODE == 1) {
        #pragma unroll
        for (int i = 0; i < 4; i++) {
            #pragma unroll
            for (int j = 0; j < 4; j++) {
                int col  = e0 + wn * 32 + j * 8 + tig * 2;
                int row0 = m0 + wm * 64 + i * 16 + gid;
                int row1 = row0 + 8;
                float2 bz = *(const float2*)(bias + col);
                float2 v0 = make_float2(acc[i][j][0] + bz.x, acc[i][j][1] + bz.y);
                float2 v1 = make_float2(acc[i][j][2] + bz.x, acc[i][j][3] + bz.y);
                if (row0 < Mc) *(float2*)(outp + (size_t)row0 * Dc + col) = v0;
                if (row1 < Mc) *(float2*)(outp + (size_t)row1 * Dc + col) = v1;
            }
        }
    } else {
        // which (q/k/v) is uniform across the block: e0 multiple of 128, Dc = 6*128
        const int which = e0 / Dc;
        __nv_bfloat16* dH = (which == 0) ? g_qh : (which == 1) ? g_kh : g_vh;
        __nv_bfloat16* dL = (which == 0) ? g_ql : (which == 1) ? g_kl : g_vl;
        #pragma unroll
        for (int i = 0; i < 4; i++) {
            #pragma unroll
            for (int j = 0; j < 4; j++) {
                int col = e0 + wn * 32 + j * 8 + tig * 2;
                int rem = col - which * Dc;
                int h = rem >> 6, d = rem & 63;
                int f = (d >> 1) & 15;
                float invf = expf(-(float)f * 0.5756462732485114f);
                #pragma unroll
                for (int rr = 0; rr < 2; rr++) {
                    int row = m0 + wm * 64 + i * 16 + gid + rr * 8;
                    if (row >= Mc) continue;
                    int b = row / Nc, n = row - b * Nc;
                    float x0 = acc[i][j][rr * 2], x1 = acc[i][j][rr * 2 + 1];
                    float o0, o1;
                    if (which < 2) {
                        int pos = 0;
                        if (n != 0) {
                            int p = n - 1;
                            pos = (d < 32) ? (p >> 5) : (p & 31);
                        }
                        float sn, cs;
                        sincosf((float)pos * invf, &sn, &cs);
                        o0 = x0 * cs - x1 * sn;
                        o1 = x1 * cs + x0 * sn;
                        if (which == 0) { o0 *= 0.125f; o1 *= 0.125f; }
                    } else {
                        o0 = x0; o1 = x1;
                    }
                    size_t dst = (((size_t)(b * Hc + h)) * Nc + n) * HDc + d;
                    uint32_t hp, lp;
                    split_pair(o0, o1, hp, lp);
                    *(uint32_t*)(dH + dst) = hp;
                    *(uint32_t*)(dL + dst) = lp;
                }
            }
        }
    }
}

// ---------------- 3) Flash attention, mma.sync 3xBF16 ------------------------
__global__ __launch_bounds__(256, 1) void attn2_k()
{
    extern __shared__ char sm[];
    const uint32_t sb = smem_u32(sm);
    const int tid = threadIdx.x, wid = tid >> 5, lane = tid & 31;
    const int bh = blockIdx.x, q0 = blockIdx.y * AQ;
    const int bI = bh / Hc, hI = bh % Hc;
    const size_t hb = (size_t)bh * Nc * HDc;
    const uint32_t Qh = sb + 2 * KVSTAGE, Ql = Qh + QARR;

    // Q tile -> smem (group 0)
    {
        const __nv_bfloat16* qhp = g_qh + hb + (size_t)q0 * HDc;
        const __nv_bfloat16* qlp = g_ql + hb + (size_t)q0 * HDc;
        #pragma unroll
        for (int t = 0; t < 4; t++) {
            int idx = tid + t * 256;
            int r = idx >> 3, c = idx & 7;
            cp16(swz(Qh, r, c), qhp + (size_t)r * HDc + c * 8);
            cp16(swz(Ql, r, c), qlp + (size_t)r * HDc + c * 8);
        }
        cp_commit();
    }
    auto load_kv = [&](int s, int kt) {
        uint32_t st = sb + s * KVSTAGE;
        const size_t kb = hb + (size_t)kt * 64 * HDc;
        #pragma unroll
        for (int t = 0; t < 2; t++) {
            int idx = tid + t * 256;
            int r = idx >> 3, c = idx & 7;
            size_t go = kb + (size_t)r * HDc + c * 8;
            cp16(swz(st,             r, c), g_kh + go);
            cp16(swz(st +     KVARR, r, c), g_kl + go);
            cp16(swz(st + 2 * KVARR, r, c), g_vh + go);
            cp16(swz(st + 3 * KVARR, r, c), g_vl + go);
        }
        cp_commit();
    };
    load_kv(0, 0);

    cp_wait<1>();      // Q group done
    __syncthreads();
    uint32_t qh[4][4], ql[4][4];
    #pragma unroll
    for (int c = 0; c < 4; c++) {
        int row = wid * 16 + (lane & 15);
        int ch  = c * 2 + (lane >> 4);
        LDM4(qh[c][0], qh[c][1], qh[c][2], qh[c][3], swz(Qh, row, ch));
        LDM4(ql[c][0], ql[c][1], ql[c][2], ql[c][3], swz(Ql, row, ch));
    }

    float out[8][4];
    #pragma unroll
    for (int i = 0; i < 8; i++)
        #pragma unroll
        for (int q = 0; q < 4; q++) out[i][q] = 0.f;
    float m0 = -1e30f, m1 = -1e30f, l0 = 0.f, l1 = 0.f;

    const int NT = (Nc + 63) / 64;   // 17
    for (int kt = 0; kt < NT; kt++) {
        if (kt + 1 < NT) load_kv((kt + 1) & 1, kt + 1);
        if (kt + 1 < NT) cp_wait<1>(); else cp_wait<0>();
        __syncthreads();
        const uint32_t st = sb + (kt & 1) * KVSTAGE;
        const uint32_t Kh = st, Kl = st + KVARR, Vh = st + 2 * KVARR, Vl = st + 3 * KVARR;

        // ---- S = Q K^T ----
        float sac[8][4];
        #pragma unroll
        for (int i = 0; i < 8; i++)
            #pragma unroll
            for (int q = 0; q < 4; q++) sac[i][q] = 0.f;
        #pragma unroll
        for (int c = 0; c < 4; c++) {
            #pragma unroll
            for (int g = 0; g < 4; g++) {
                int row = g * 16 + (lane & 15);
                int ch  = c * 2 + (lane >> 4);
                uint32_t kh0, kh1, kh2, kh3, kl0, kl1, kl2, kl3;
                LDM4(kh0, kh1, kh2, kh3, swz(Kh, row, ch));
                LDM4(kl0, kl1, kl2, kl3, swz(Kl, row, ch));
                MMA16816(sac[2 * g],     qh[c], kh0, kh2);
                MMA16816(sac[2 * g],     qh[c], kl0, kl2);
                MMA16816(sac[2 * g],     ql[c], kh0, kh2);
                MMA16816(sac[2 * g + 1], qh[c], kh1, kh3);
                MMA16816(sac[2 * g + 1], qh[c], kl1, kl3);
                MMA16816(sac[2 * g + 1], ql[c], kh1, kh3);
            }
        }
        // ---- mask ----
        const int k0 = kt * 64;
        #pragma unroll
        for (int j = 0; j < 8; j++) {
            int kc = k0 + j * 8 + 2 * (lane & 3);
            if (kc     >= Nc) { sac[j][0] = -1e30f; sac[j][2] = -1e30f; }
            if (kc + 1 >= Nc) { sac[j][1] = -1e30f; sac[j][3] = -1e30f; }
        }
        // ---- online softmax ----
        float mx0 = -1e30f, mx1 = -1e30f;
        #pragma unroll
        for (int j = 0; j < 8; j++) {
            mx0 = fmaxf(mx0, fmaxf(sac[j][0], sac[j][1]));
            mx1 = fmaxf(mx1, fmaxf(sac[j][2], sac[j][3]));
        }
        mx0 = fmaxf(mx0, __shfl_xor_sync(0xffffffffu, mx0, 1));
        mx0 = fmaxf(mx0, __shfl_xor_sync(0xffffffffu, mx0, 2));
        mx1 = fmaxf(mx1, __shfl_xor_sync(0xffffffffu, mx1, 1));
        mx1 = fmaxf(mx1, __shfl_xor_sync(0xffffffffu, mx1, 2));
        float mn0 = fmaxf(m0, mx0), mn1 = fmaxf(m1, mx1);
        float co0 = __expf(m0 - mn0), co1 = __expf(m1 - mn1);
        m0 = mn0; m1 = mn1;
        float rs0 = 0.f, rs1 = 0.f;
        #pragma unroll
        for (int j = 0; j < 8; j++) {
            sac[j][0] = __expf(sac[j][0] - mn0);
            sac[j][1] = __expf(sac[j][1] - mn0);
            sac[j][2] = __expf(sac[j][2] - mn1);
            sac[j][3] = __expf(sac[j][3] - mn1);
            rs0 += sac[j][0] + sac[j][1];
            rs1 += sac[j][2] + sac[j][3];
        }
        rs0 += __shfl_xor_sync(0xffffffffu, rs0, 1);
        rs0 += __shfl_xor_sync(0xffffffffu, rs0, 2);
        rs1 += __shfl_xor_sync(0xffffffffu, rs1, 1);
        rs1 += __shfl_xor_sync(0xffffffffu, rs1, 2);
        l0 = l0 * co0 + rs0;
        l1 = l1 * co1 + rs1;
        #pragma unroll
        for (int jd = 0; jd < 8; jd++) {
            out[jd][0] *= co0; out[jd][1] *= co0;
            out[jd][2] *= co1; out[jd][3] *= co1;
        }
        // ---- O += P V ----
        #pragma unroll
        for (int kc2 = 0; kc2 < 4; kc2++) {
            uint32_t AH[4], AL[4];
            split_pair(sac[2 * kc2][0],     sac[2 * kc2][1],     AH[0], AL[0]);
            split_pair(sac[2 * kc2][2],     sac[2 * kc2][3],     AH[1], AL[1]);
            split_pair(sac[2 * kc2 + 1][0], sac[2 * kc2 + 1][1], AH[2], AL[2]);
            split_pair(sac[2 * kc2 + 1][2], sac[2 * kc2 + 1][3], AH[3], AL[3]);
            #pragma unroll
            for (int jd = 0; jd < 4; jd++) {
                int row = kc2 * 16 + (lane & 15);
                int ch  = jd * 2 + (lane >> 4);
                uint32_t v0, v1, v2, v3, w0, w1, w2, w3;
                LDM4T(v0, v1, v2, v3, swz(Vh, row, ch));
                LDM4T(w0, w1, w2, w3, swz(Vl, row, ch));
                MMA16816(out[2 * jd],     AH, v0, v1);
                MMA16816(out[2 * jd],     AH, w0, w1);
                MMA16816(out[2 * jd],     AL, v0, v1);
                MMA16816(out[2 * jd + 1], AH, v2, v3);
                MMA16816(out[2 * jd + 1], AH, w2, w3);
                MMA16816(out[2 * jd + 1], AL, v2, v3);
            }
        }
        __syncthreads();
    }
    // ---- epilogue: normalize, split, store bf16 hi/lo to [m][h*64+d] ----
    const float inv0 = 1.f / l0, inv1 = 1.f / l1;
    const int r = q0 + wid * 16 + (lane >> 2);
    #pragma unroll
    for (int jd = 0; jd < 8; jd++) {
        int col = hI * 64 + jd * 8 + 2 * (lane & 3);
        if (r < Nc) {
            size_t mi = ((size_t)(bI * Nc + r)) * Dc + col;
            uint32_t hp, lp;
            split_pair(out[jd][0] * inv0, out[jd][1] * inv0, hp, lp);
            *(uint32_t*)(g_ohi + mi) = hp;
            *(uint32_t*)(g_olo + mi) = lp;
        }
        if (r + 8 < Nc) {
            size_t mi = ((size_t)(bI * Nc + r + 8)) * Dc + col;
            uint32_t hp, lp;
            split_pair(out[jd][2] * inv1, out[jd][3] * inv1, hp, lp);
            *(uint32_t*)(g_ohi + mi) = hp;
            *(uint32_t*)(g_olo + mi) = lp;
        }
    }
}

// ---------------- launch ------------------------------------------------------
extern "C" void kernel_launch(void* const* d_in, const int* in_sizes, int n_in,
                              void* d_out, int out_size)
{
    const float* x  = (const float*)d_in[0];
    const float* lg = (const float*)d_in[1];
    const float* lb = (const float*)d_in[2];
    const float* wq = (const float*)d_in[3];
    const float* wp = (const float*)d_in[4];
    const float* bp = (const float*)d_in[5];
    float* out = (float*)d_out;
    (void)in_sizes; (void)n_in; (void)out_size;

    cudaFuncSetAttribute(mma_gemm_k<0>, cudaFuncAttributeMaxDynamicSharedMemorySize, GEMM_SMEM);
    cudaFuncSetAttribute(mma_gemm_k<1>, cudaFuncAttributeMaxDynamicSharedMemorySize, GEMM_SMEM);
    cudaFuncSetAttribute(attn2_k, cudaFuncAttributeMaxDynamicSharedMemorySize, ATTN_SMEM);

    lnsplit_k<<<Mc, 256>>>(x, lg, lb);
    split_w_k<0><<<(E3c * Dc + 255) / 256, 256>>>(wq, E3c * Dc);
    split_w_k<1><<<(Dc * Dc + 255) / 256, 256>>>(wp, Dc * Dc);
    zero_pad_k<<<(PADR * HDc + 255) / 256, 256>>>();
    mma_gemm_k<0><<<dim3(E3c / BN, MP / BM), 256, GEMM_SMEM>>>(nullptr, nullptr);
    attn2_k<<<dim3(Bc * Hc, (Nc + AQ - 1) / AQ), 256, ATTN_SMEM>>>();
    mma_gemm_k<1><<<dim3(Dc / BN, MP / BM), 256, GEMM_SMEM>>>(bp, out);
}

// round 13
// speedup vs baseline: 3.3461x; 1.1162x over previous
#include <cuda_runtime.h>
#include <cuda_fp16.h>
#include <cstdint>
#include <math.h>

#define Bc   8
#define Nc   1025
#define Dc   768
#define Hc   12
#define HDc  64
#define E3c  2304
#define Mc   (Bc*Nc)      // 8200
#define MP   8320         // M padded to 65*128

#define WSCALE 256.0f
#define INVW   (1.0f/256.0f)

// ---- mma.sync gemm config ----
#define BM 128
#define BN 128
#define BK 32
#define NK (Dc/BK)              // 24
#define ROWB 80
#define ARR_BYTES (128*ROWB)
#define STAGE_BYTES (4*ARR_BYTES)
#define GEMM_SMEM (2*STAGE_BYTES) // 81920

// ---- attention config ----
#define AQ 128
#define PADR 128
#define KVARR 8192              // 64 rows * 128B
#define KVSTAGE (4*KVARR)       // Kh,Kl,Vh,Vl
#define QARR 16384              // 128 rows * 128B
#define ATTN_SMEM (2*KVSTAGE + 2*QARR)  // 98304

// ---------------- scratch ----------------
__device__ __half g_ahi[(size_t)MP * Dc];
__device__ __half g_alo[(size_t)MP * Dc];
__device__ __half g_oh [(size_t)MP * Dc];          // attn out, rounded fp16
__device__ __half g_wqhi[(size_t)E3c * Dc];
__device__ __half g_wqlo[(size_t)E3c * Dc];
__device__ __half g_wphi[(size_t)Dc * Dc];
__device__ __half g_wplo[(size_t)Dc * Dc];
// attention operands, fp16 hi/lo, [B,H,N,64] (+pad rows)
#define QKV_ROWS ((size_t)Bc*Hc*Nc + PADR)
__device__ __half g_qh[QKV_ROWS * HDc];
__device__ __half g_ql[QKV_ROWS * HDc];
__device__ __half g_kh[QKV_ROWS * HDc];
__device__ __half g_kl[QKV_ROWS * HDc];
__device__ __half g_vh[QKV_ROWS * HDc];
__device__ __half g_vl[QKV_ROWS * HDc];

// ================= helpers =================
__device__ __forceinline__ uint32_t smem_u32(const void* p) {
    uint32_t a;
    asm("{ .reg .u64 t; cvta.to.shared.u64 t, %1; cvt.u32.u64 %0, t; }"
        : "=r"(a) : "l"(p));
    return a;
}

#define LDM4(r0, r1, r2, r3, addr) \
    asm volatile("ldmatrix.sync.aligned.m8n8.x4.shared.b16 {%0,%1,%2,%3}, [%4];" \
        : "=r"(r0), "=r"(r1), "=r"(r2), "=r"(r3) : "r"(addr))

#define LDM4T(r0, r1, r2, r3, addr) \
    asm volatile("ldmatrix.sync.aligned.m8n8.x4.trans.shared.b16 {%0,%1,%2,%3}, [%4];" \
        : "=r"(r0), "=r"(r1), "=r"(r2), "=r"(r3) : "r"(addr))

#define MMA16816(d, a, b0, b1) \
    asm volatile("mma.sync.aligned.m16n8k16.row.col.f32.f16.f16.f32 " \
        "{%0,%1,%2,%3}, {%4,%5,%6,%7}, {%8,%9}, {%0,%1,%2,%3};" \
        : "+f"((d)[0]), "+f"((d)[1]), "+f"((d)[2]), "+f"((d)[3]) \
        : "r"((a)[0]), "r"((a)[1]), "r"((a)[2]), "r"((a)[3]), "r"(b0), "r"(b1))

__device__ __forceinline__ void cp16(uint32_t dst, const void* src) {
    asm volatile("cp.async.cg.shared.global [%0], [%1], 16;" :: "r"(dst), "l"(src));
}
__device__ __forceinline__ void cp_commit() {
    asm volatile("cp.async.commit_group;" ::: "memory");
}
template<int N>
__device__ __forceinline__ void cp_wait() {
    asm volatile("cp.async.wait_group %0;" :: "n"(N) : "memory");
}

// pack two fp32 -> fp16x2 {lo=x, hi=y}
__device__ __forceinline__ uint32_t pack_h2(float x, float y) {
    __half2 h = __floats2half2_rn(x, y);
    return *reinterpret_cast<uint32_t*>(&h);
}
// hi/lo split of a pair
__device__ __forceinline__ void split_pair(float x, float y, uint32_t& hp, uint32_t& lp) {
    __half2 h = __floats2half2_rn(x, y);
    hp = *reinterpret_cast<uint32_t*>(&h);
    float2 hf = __half22float2(h);
    lp = pack_h2(x - hf.x, y - hf.y);
}

__device__ __forceinline__ uint32_t swz(uint32_t base, int row, int chunk) {
    return base + row * 128 + ((chunk ^ (row & 7)) << 4);
}

// ---------------- 1) LayerNorm + fp16 hi/lo split (fused) --------------------
__global__ __launch_bounds__(256) void lnsplit_k(
    const float* __restrict__ x, const float* __restrict__ lg, const float* __restrict__ lb)
{
    const int row = blockIdx.x;
    const float* xr = x + (size_t)row * Dc;
    float v3[3];
    float s = 0.f, s2 = 0.f;
    #pragma unroll
    for (int t = 0; t < 3; t++) {
        float v = xr[threadIdx.x + t * 256];
        v3[t] = v;
        s += v; s2 += v * v;
    }
    #pragma unroll
    for (int o = 16; o; o >>= 1) {
        s  += __shfl_xor_sync(0xffffffffu, s,  o);
        s2 += __shfl_xor_sync(0xffffffffu, s2, o);
    }
    __shared__ float sh[16];
    __shared__ float smu, srs;
    const int w = threadIdx.x >> 5;
    if ((threadIdx.x & 31) == 0) { sh[w] = s; sh[8 + w] = s2; }
    __syncthreads();
    if (threadIdx.x < 32) {
        s  = (threadIdx.x < 8) ? sh[threadIdx.x]     : 0.f;
        s2 = (threadIdx.x < 8) ? sh[8 + threadIdx.x] : 0.f;
        #pragma unroll
        for (int o = 4; o; o >>= 1) {
            s  += __shfl_xor_sync(0xffffffffu, s,  o);
            s2 += __shfl_xor_sync(0xffffffffu, s2, o);
        }
        if (threadIdx.x == 0) {
            float mu  = s  * (1.f / Dc);
            float var = s2 * (1.f / Dc) - mu * mu;
            smu = mu;
            srs = rsqrtf(var + 1e-5f);
        }
    }
    __syncthreads();
    const float mu = smu, rs = srs;
    #pragma unroll
    for (int t = 0; t < 3; t++) {
        int c = threadIdx.x + t * 256;
        float v = (v3[t] - mu) * rs * lg[c] + lb[c];
        __half h = __float2half_rn(v);
        g_ahi[(size_t)row * Dc + c] = h;
        g_alo[(size_t)row * Dc + c] = __float2half_rn(v - __half2float(h));
    }
}

// weights * 256 -> fp16 hi/lo
template<int WHICH>
__global__ void split_w_k(const float* __restrict__ w, int n)
{
    int i = blockIdx.x * 256 + threadIdx.x;
    if (i >= n) return;
    float v = w[i] * WSCALE;
    __half h = __float2half_rn(v);
    __half l = __float2half_rn(v - __half2float(h));
    if (WHICH == 0) { g_wqhi[i] = h; g_wqlo[i] = l; }
    else            { g_wphi[i] = h; g_wplo[i] = l; }
}

__global__ void zero_pad_k()
{
    int i = blockIdx.x * 256 + threadIdx.x;
    if (i >= PADR * HDc) return;
    size_t off = (size_t)Bc * Hc * Nc * HDc + i;
    __half z = __float2half_rn(0.f);
    g_qh[off] = z; g_ql[off] = z;
    g_kh[off] = z; g_kl[off] = z;
    g_vh[off] = z; g_vl[off] = z;
}

// ---------------- 2) mma.sync fp16 GEMM --------------------------------------
// MODE 0 (3-product): QKV gemm; epilogue: scale 1/256, RoPE, split -> g_q/k/v
// MODE 1 (2-product): out = O_fp16 @ (wp*256)^T / 256 + bias
template<int MODE>
__global__ __launch_bounds__(256, 2) void mma_gemm_k(
    const float* __restrict__ bias, float* __restrict__ outp)
{
    const __half* __restrict__ Ahi = (MODE == 0) ? g_ahi : g_oh;
    const __half* __restrict__ Alo = (MODE == 0) ? g_alo : g_oh;   // unused if MODE 1
    const __half* __restrict__ Bhi = (MODE == 0) ? g_wqhi : g_wphi;
    const __half* __restrict__ Blo = (MODE == 0) ? g_wqlo : g_wplo;

    extern __shared__ char smem[];
    const uint32_t sb = smem_u32(smem);
    const int tid  = threadIdx.x;
    const int wid  = tid >> 5;
    const int lane = tid & 31;
    const int wm = wid >> 2;
    const int wn = wid & 3;
    const int e0 = blockIdx.x * BN;
    const int m0 = blockIdx.y * BM;

    const __half* gA[4] = {
        Ahi + (size_t)m0 * Dc, Alo + (size_t)m0 * Dc,
        Bhi + (size_t)e0 * Dc, Blo + (size_t)e0 * Dc };

    auto load_stage = [&](int s, int k0) {
        const uint32_t stg = sb + s * STAGE_BYTES;
        #pragma unroll
        for (int arr = 0; arr < 4; arr++) {
            if (MODE == 1 && arr == 1) continue;
            #pragma unroll
            for (int i = 0; i < 2; i++) {
                int ci = tid + i * 256;
                int r = ci >> 2, c = ci & 3;
                cp16(stg + arr * ARR_BYTES + r * ROWB + c * 16,
                     gA[arr] + (size_t)r * Dc + k0 + c * 8);
            }
        }
        cp_commit();
    };

    float acc[4][4][4];
    #pragma unroll
    for (int i = 0; i < 4; i++)
        #pragma unroll
        for (int j = 0; j < 4; j++)
            #pragma unroll
            for (int q = 0; q < 4; q++) acc[i][j][q] = 0.f;

    const int a_row   = (lane & 7) + ((lane >> 3) & 1) * 8;
    const int a_chunk = (lane >> 4) & 1;
    const int b_row   = (lane & 7) + ((lane >> 4) & 1) * 8;
    const int b_chunk = (lane >> 3) & 1;

    load_stage(0, 0);

    for (int it = 0; it < NK; it++) {
        if (it + 1 < NK) load_stage((it + 1) & 1, (it + 1) * BK);
        if (it + 1 < NK) cp_wait<1>(); else cp_wait<0>();
        __syncthreads();

        const uint32_t stg = sb + (it & 1) * STAGE_BYTES;
        const uint32_t aHi = stg;
        const uint32_t aLo = stg + ARR_BYTES;
        const uint32_t bHi = stg + 2 * ARR_BYTES;
        const uint32_t bLo = stg + 3 * ARR_BYTES;

        #pragma unroll
        for (int k16 = 0; k16 < 2; k16++) {
            uint32_t ah[4][4], al[4][4], bh[2][4], bl[2][4];
            #pragma unroll
            for (int i = 0; i < 4; i++) {
                uint32_t ro = (uint32_t)((wm * 64 + i * 16 + a_row) * ROWB
                                         + (k16 * 2 + a_chunk) * 16);
                LDM4(ah[i][0], ah[i][1], ah[i][2], ah[i][3], aHi + ro);
                if (MODE == 0) {
                    LDM4(al[i][0], al[i][1], al[i][2], al[i][3], aLo + ro);
                }
            }
            #pragma unroll
            for (int j2 = 0; j2 < 2; j2++) {
                uint32_t ro = (uint32_t)((wn * 32 + j2 * 16 + b_row) * ROWB
                                         + (k16 * 2 + b_chunk) * 16);
                LDM4(bh[j2][0], bh[j2][1], bh[j2][2], bh[j2][3], bHi + ro);
                LDM4(bl[j2][0], bl[j2][1], bl[j2][2], bl[j2][3], bLo + ro);
            }
            #pragma unroll
            for (int i = 0; i < 4; i++) {
                #pragma unroll
                for (int j = 0; j < 4; j++) {
                    uint32_t h0 = bh[j >> 1][(j & 1) * 2];
                    uint32_t h1 = bh[j >> 1][(j & 1) * 2 + 1];
                    uint32_t l0 = bl[j >> 1][(j & 1) * 2];
                    uint32_t l1 = bl[j >> 1][(j & 1) * 2 + 1];
                    MMA16816(acc[i][j], ah[i], h0, h1);
                    MMA16816(acc[i][j], ah[i], l0, l1);
                    if (MODE == 0) {
                        MMA16816(acc[i][j], al[i], h0, h1);
                    }
                }
            }
        }
        __syncthreads();
    }

    // ---- epilogue ----
    const int gid = lane >> 2, tig = lane & 3;
    if (MODE == 1) {
        #pragma unroll
        for (int i = 0; i < 4; i++) {
            #pragma unroll
            for (int j = 0; j < 4; j++) {
                int col  = e0 + wn * 32 + j * 8 + tig * 2;
                int row0 = m0 + wm * 64 + i * 16 + gid;
                int row1 = row0 + 8;
                float2 bz = *(const float2*)(bias + col);
                float2 v0 = make_float2(acc[i][j][0] * INVW + bz.x, acc[i][j][1] * INVW + bz.y);
                float2 v1 = make_float2(acc[i][j][2] * INVW + bz.x, acc[i][j][3] * INVW + bz.y);
                if (row0 < Mc) *(float2*)(outp + (size_t)row0 * Dc + col) = v0;
                if (row1 < Mc) *(float2*)(outp + (size_t)row1 * Dc + col) = v1;
            }
        }
    } else {
        const int which = e0 / Dc;
        __half* dH = (which == 0) ? g_qh : (which == 1) ? g_kh : g_vh;
        __half* dL = (which == 0) ? g_ql : (which == 1) ? g_kl : g_vl;
        #pragma unroll
        for (int i = 0; i < 4; i++) {
            #pragma unroll
            for (int j = 0; j < 4; j++) {
                int col = e0 + wn * 32 + j * 8 + tig * 2;
                int rem = col - which * Dc;
                int h = rem >> 6, d = rem & 63;
                int f = (d >> 1) & 15;
                float invf = expf(-(float)f * 0.5756462732485114f);
                #pragma unroll
                for (int rr = 0; rr < 2; rr++) {
                    int row = m0 + wm * 64 + i * 16 + gid + rr * 8;
                    if (row >= Mc) continue;
                    int b = row / Nc, n = row - b * Nc;
                    float x0 = acc[i][j][rr * 2] * INVW, x1 = acc[i][j][rr * 2 + 1] * INVW;
                    float o0, o1;
                    if (which < 2) {
                        int pos = 0;
                        if (n != 0) {
                            int p = n - 1;
                            pos = (d < 32) ? (p >> 5) : (p & 31);
                        }
                        float sn, cs;
                        sincosf((float)pos * invf, &sn, &cs);
                        o0 = x0 * cs - x1 * sn;
                        o1 = x1 * cs + x0 * sn;
                    } else {
                        o0 = x0; o1 = x1;
                    }
                    size_t dst = (((size_t)(b * Hc + h)) * Nc + n) * HDc + d;
                    uint32_t hp, lp;
                    split_pair(o0, o1, hp, lp);
                    *(uint32_t*)(dH + dst) = hp;
                    *(uint32_t*)(dL + dst) = lp;
                }
            }
        }
    }
}

// ---------------- 3) Flash attention, mma.sync fp16 --------------------------
// S = QK^T: 3-product; scale 1/8 applied post-MMA. PV: 2-product (P rounded).
__global__ __launch_bounds__(256, 1) void attn2_k()
{
    extern __shared__ char sm[];
    const uint32_t sb = smem_u32(sm);
    const int tid = threadIdx.x, wid = tid >> 5, lane = tid & 31;
    const int bh = blockIdx.x, q0 = blockIdx.y * AQ;
    const int bI = bh / Hc, hI = bh % Hc;
    const size_t hb = (size_t)bh * Nc * HDc;
    const uint32_t Qh = sb + 2 * KVSTAGE, Ql = Qh + QARR;

    {
        const __half* qhp = g_qh + hb + (size_t)q0 * HDc;
        const __half* qlp = g_ql + hb + (size_t)q0 * HDc;
        #pragma unroll
        for (int t = 0; t < 4; t++) {
            int idx = tid + t * 256;
            int r = idx >> 3, c = idx & 7;
            cp16(swz(Qh, r, c), qhp + (size_t)r * HDc + c * 8);
            cp16(swz(Ql, r, c), qlp + (size_t)r * HDc + c * 8);
        }
        cp_commit();
    }
    auto load_kv = [&](int s, int kt) {
        uint32_t st = sb + s * KVSTAGE;
        const size_t kb = hb + (size_t)kt * 64 * HDc;
        #pragma unroll
        for (int t = 0; t < 2; t++) {
            int idx = tid + t * 256;
            int r = idx >> 3, c = idx & 7;
            size_t go = kb + (size_t)r * HDc + c * 8;
            cp16(swz(st,             r, c), g_kh + go);
            cp16(swz(st +     KVARR, r, c), g_kl + go);
            cp16(swz(st + 2 * KVARR, r, c), g_vh + go);
            cp16(swz(st + 3 * KVARR, r, c), g_vl + go);
        }
        cp_commit();
    };
    load_kv(0, 0);

    cp_wait<1>();
    __syncthreads();
    uint32_t qh[4][4], ql[4][4];
    #pragma unroll
    for (int c = 0; c < 4; c++) {
        int row = wid * 16 + (lane & 15);
        int ch  = c * 2 + (lane >> 4);
        LDM4(qh[c][0], qh[c][1], qh[c][2], qh[c][3], swz(Qh, row, ch));
        LDM4(ql[c][0], ql[c][1], ql[c][2], ql[c][3], swz(Ql, row, ch));
    }

    float out[8][4];
    #pragma unroll
    for (int i = 0; i < 8; i++)
        #pragma unroll
        for (int q = 0; q < 4; q++) out[i][q] = 0.f;
    float m0 = -1e30f, m1 = -1e30f, l0 = 0.f, l1 = 0.f;

    const int NT = (Nc + 63) / 64;   // 17
    for (int kt = 0; kt < NT; kt++) {
        if (kt + 1 < NT) load_kv((kt + 1) & 1, kt + 1);
        if (kt + 1 < NT) cp_wait<1>(); else cp_wait<0>();
        __syncthreads();
        const uint32_t st = sb + (kt & 1) * KVSTAGE;
        const uint32_t Kh = st, Kl = st + KVARR, Vh = st + 2 * KVARR, Vl = st + 3 * KVARR;

        // ---- S = Q K^T (3-product fp16) ----
        float sac[8][4];
        #pragma unroll
        for (int i = 0; i < 8; i++)
            #pragma unroll
            for (int q = 0; q < 4; q++) sac[i][q] = 0.f;
        #pragma unroll
        for (int c = 0; c < 4; c++) {
            #pragma unroll
            for (int g = 0; g < 4; g++) {
                int row = g * 16 + (lane & 15);
                int ch  = c * 2 + (lane >> 4);
                uint32_t kh0, kh1, kh2, kh3, kl0, kl1, kl2, kl3;
                LDM4(kh0, kh1, kh2, kh3, swz(Kh, row, ch));
                LDM4(kl0, kl1, kl2, kl3, swz(Kl, row, ch));
                MMA16816(sac[2 * g],     qh[c], kh0, kh2);
                MMA16816(sac[2 * g],     qh[c], kl0, kl2);
                MMA16816(sac[2 * g],     ql[c], kh0, kh2);
                MMA16816(sac[2 * g + 1], qh[c], kh1, kh3);
                MMA16816(sac[2 * g + 1], qh[c], kl1, kl3);
                MMA16816(sac[2 * g + 1], ql[c], kh1, kh3);
            }
        }
        // ---- scale + mask ----
        const int k0 = kt * 64;
        #pragma unroll
        for (int j = 0; j < 8; j++) {
            sac[j][0] *= 0.125f; sac[j][1] *= 0.125f;
            sac[j][2] *= 0.125f; sac[j][3] *= 0.125f;
            int kc = k0 + j * 8 + 2 * (lane & 3);
            if (kc     >= Nc) { sac[j][0] = -1e30f; sac[j][2] = -1e30f; }
            if (kc + 1 >= Nc) { sac[j][1] = -1e30f; sac[j][3] = -1e30f; }
        }
        // ---- online softmax ----
        float mx0 = -1e30f, mx1 = -1e30f;
        #pragma unroll
        for (int j = 0; j < 8; j++) {
            mx0 = fmaxf(mx0, fmaxf(sac[j][0], sac[j][1]));
            mx1 = fmaxf(mx1, fmaxf(sac[j][2], sac[j][3]));
        }
        mx0 = fmaxf(mx0, __shfl_xor_sync(0xffffffffu, mx0, 1));
        mx0 = fmaxf(mx0, __shfl_xor_sync(0xffffffffu, mx0, 2));
        mx1 = fmaxf(mx1, __shfl_xor_sync(0xffffffffu, mx1, 1));
        mx1 = fmaxf(mx1, __shfl_xor_sync(0xffffffffu, mx1, 2));
        float mn0 = fmaxf(m0, mx0), mn1 = fmaxf(m1, mx1);
        float co0 = __expf(m0 - mn0), co1 = __expf(m1 - mn1);
        m0 = mn0; m1 = mn1;
        float rs0 = 0.f, rs1 = 0.f;
        #pragma unroll
        for (int j = 0; j < 8; j++) {
            sac[j][0] = __expf(sac[j][0] - mn0);
            sac[j][1] = __expf(sac[j][1] - mn0);
            sac[j][2] = __expf(sac[j][2] - mn1);
            sac[j][3] = __expf(sac[j][3] - mn1);
            rs0 += sac[j][0] + sac[j][1];
            rs1 += sac[j][2] + sac[j][3];
        }
        rs0 += __shfl_xor_sync(0xffffffffu, rs0, 1);
        rs0 += __shfl_xor_sync(0xffffffffu, rs0, 2);
        rs1 += __shfl_xor_sync(0xffffffffu, rs1, 1);
        rs1 += __shfl_xor_sync(0xffffffffu, rs1, 2);
        l0 = l0 * co0 + rs0;
        l1 = l1 * co1 + rs1;
        #pragma unroll
        for (int jd = 0; jd < 8; jd++) {
            out[jd][0] *= co0; out[jd][1] *= co0;
            out[jd][2] *= co1; out[jd][3] *= co1;
        }
        // ---- O += P V (2-product: P rounded, V hi/lo) ----
        #pragma unroll
        for (int kc2 = 0; kc2 < 4; kc2++) {
            uint32_t AH[4];
            AH[0] = pack_h2(sac[2 * kc2][0],     sac[2 * kc2][1]);
            AH[1] = pack_h2(sac[2 * kc2][2],     sac[2 * kc2][3]);
            AH[2] = pack_h2(sac[2 * kc2 + 1][0], sac[2 * kc2 + 1][1]);
            AH[3] = pack_h2(sac[2 * kc2 + 1][2], sac[2 * kc2 + 1][3]);
            #pragma unroll
            for (int jd = 0; jd < 4; jd++) {
                int row = kc2 * 16 + (lane & 15);
                int ch  = jd * 2 + (lane >> 4);
                uint32_t v0, v1, v2, v3, w0, w1, w2, w3;
                LDM4T(v0, v1, v2, v3, swz(Vh, row, ch));
                LDM4T(w0, w1, w2, w3, swz(Vl, row, ch));
                MMA16816(out[2 * jd],     AH, v0, v1);
                MMA16816(out[2 * jd],     AH, w0, w1);
                MMA16816(out[2 * jd + 1], AH, v2, v3);
                MMA16816(out[2 * jd + 1], AH, w2, w3);
            }
        }
        __syncthreads();
    }
    // ---- epilogue: normalize, round to fp16, store ----
    const float inv0 = 1.f / l0, inv1 = 1.f / l1;
    const int r = q0 + wid * 16 + (lane >> 2);
    #pragma unroll
    for (int jd = 0; jd < 8; jd++) {
        int col = hI * 64 + jd * 8 + 2 * (lane & 3);
        if (r < Nc) {
            size_t mi = ((size_t)(bI * Nc + r)) * Dc + col;
            *(uint32_t*)(g_oh + mi) = pack_h2(out[jd][0] * inv0, out[jd][1] * inv0);
        }
        if (r + 8 < Nc) {
            size_t mi = ((size_t)(bI * Nc + r + 8)) * Dc + col;
            *(uint32_t*)(g_oh + mi) = pack_h2(out[jd][2] * inv1, out[jd][3] * inv1);
        }
    }
}

// ---------------- launch ------------------------------------------------------
extern "C" void kernel_launch(void* const* d_in, const int* in_sizes, int n_in,
                              void* d_out, int out_size)
{
    const float* x  = (const float*)d_in[0];
    const float* lg = (const float*)d_in[1];
    const float* lb = (const float*)d_in[2];
    const float* wq = (const float*)d_in[3];
    const float* wp = (const float*)d_in[4];
    const float* bp = (const float*)d_in[5];
    float* out = (float*)d_out;
    (void)in_sizes; (void)n_in; (void)out_size;

    cudaFuncSetAttribute(mma_gemm_k<0>, cudaFuncAttributeMaxDynamicSharedMemorySize, GEMM_SMEM);
    cudaFuncSetAttribute(mma_gemm_k<1>, cudaFuncAttributeMaxDynamicSharedMemorySize, GEMM_SMEM);
    cudaFuncSetAttribute(attn2_k, cudaFuncAttributeMaxDynamicSharedMemorySize, ATTN_SMEM);

    lnsplit_k<<<Mc, 256>>>(x, lg, lb);
    split_w_k<0><<<(E3c * Dc + 255) / 256, 256>>>(wq, E3c * Dc);
    split_w_k<1><<<(Dc * Dc + 255) / 256, 256>>>(wp, Dc * Dc);
    zero_pad_k<<<(PADR * HDc + 255) / 256, 256>>>();
    mma_gemm_k<0><<<dim3(E3c / BN, MP / BM), 256, GEMM_SMEM>>>(nullptr, nullptr);
    attn2_k<<<dim3(Bc * Hc, (Nc + AQ - 1) / AQ), 256, ATTN_SMEM>>>();
    mma_gemm_k<1><<<dim3(Dc / BN, MP / BM), 256, GEMM_SMEM>>>(bp, out);
}